// round 1
// baseline (speedup 1.0000x reference)
#include <cuda_runtime.h>
#include <cuda_bf16.h>
#include <math.h>
#include <float.h>

// Problem constants
#define BQ      4
#define SEQ     4096
#define DMODEL  2048
#define NH      16
#define DN      128
#define DRD     64
#define DVD     128
#define QLAT    512
#define KVLAT   512
#define MROWS   (BQ*SEQ)          // 16384
#define QW      (NH*(DN+DRD))     // 3072
#define KVAW    (KVLAT+DRD)       // 576
#define KVBW    (NH*(DN+DVD))     // 4096
#define OW      (NH*DVD)          // 2048
#define SCALE_F 0.07216878364870323f   // (128+64)^-0.5

// ---------------- scratch (device globals; no allocation allowed) ----------------
__device__ float g_qlat[MROWS*QLAT];     // 32 MB
__device__ float g_q   [MROWS*QW];       // 192 MB
__device__ float g_kva [MROWS*KVAW];     // 36 MB
__device__ float g_kvb [MROWS*KVBW];     // 256 MB
__device__ float g_kpe [MROWS*DRD];      // 4 MB
__device__ float g_attn[MROWS*OW];       // 128 MB
__device__ unsigned int g_eta_enc[256];
__device__ float g_eta[256];

// ---------------- helpers ----------------
__device__ __forceinline__ float silu_f(float x) { return x / (1.0f + expf(-x)); }

__device__ __forceinline__ unsigned encf(float f) {
    unsigned u = __float_as_uint(f);
    return (u & 0x80000000u) ? ~u : (u | 0x80000000u);
}
__device__ __forceinline__ float decf(unsigned u) {
    return (u & 0x80000000u) ? __uint_as_float(u ^ 0x80000000u) : __uint_as_float(~u);
}

// ---------------- SGEMM (NT): C[M,N] = A[M,K] @ B[N,K]^T, fp32 ----------------
// BM=128, BK=8, TM=8; BN/TN templated (128/8 main, 64/4 for N=576). 256 threads.
template<int BN, int TN>
__global__ void __launch_bounds__(256)
sgemm_nt(const float* __restrict__ A, const float* __restrict__ B,
         float* __restrict__ C, int K, int lda, int ldb, int ldc)
{
    const int BM = 128, BK = 8, TM = 8;
    __shared__ float As[BK][BM];
    __shared__ float Bs[BK][BN];

    int tid = threadIdx.x;
    int bm = blockIdx.y * BM;
    int bn = blockIdx.x * BN;

    // A tile: 128x8 = 256 float4 loads (one per thread)
    int a_m = tid >> 1;
    int a_k = (tid & 1) * 4;
    const float* Aptr = A + (size_t)(bm + a_m) * lda + a_k;

    // B tile: BN x 8 = BN*2 float4 loads
    const int BLOADS = BN * 2;
    int b_n = tid >> 1;
    int b_k = (tid & 1) * 4;
    bool bact = (tid < BLOADS);
    const float* Bptr = B + (size_t)(bn + (bact ? b_n : 0)) * ldb + b_k;

    float4 pa = *(const float4*)Aptr;
    float4 pb = bact ? *(const float4*)Bptr : make_float4(0.f,0.f,0.f,0.f);

    float acc[TM][TN];
#pragma unroll
    for (int i = 0; i < TM; i++)
#pragma unroll
        for (int j = 0; j < TN; j++) acc[i][j] = 0.f;

    const int TCOLS = BN / TN;             // 16
    int ty = tid / TCOLS;                  // 0..15 -> 8 rows each
    int tx = tid % TCOLS;                  // 0..15 -> TN cols each

    int nk = K / BK;
    for (int kt = 0; kt < nk; kt++) {
        As[a_k+0][a_m] = pa.x; As[a_k+1][a_m] = pa.y;
        As[a_k+2][a_m] = pa.z; As[a_k+3][a_m] = pa.w;
        if (bact) {
            Bs[b_k+0][b_n] = pb.x; Bs[b_k+1][b_n] = pb.y;
            Bs[b_k+2][b_n] = pb.z; Bs[b_k+3][b_n] = pb.w;
        }
        __syncthreads();
        if (kt + 1 < nk) {
            pa = *(const float4*)(Aptr + (size_t)(kt+1)*BK);
            if (bact) pb = *(const float4*)(Bptr + (size_t)(kt+1)*BK);
        }
#pragma unroll
        for (int k = 0; k < BK; k++) {
            float ar[TM], br[TN];
#pragma unroll
            for (int i = 0; i < TM; i++) ar[i] = As[k][ty*TM + i];
#pragma unroll
            for (int j = 0; j < TN; j++) br[j] = Bs[k][tx*TN + j];
#pragma unroll
            for (int i = 0; i < TM; i++)
#pragma unroll
                for (int j = 0; j < TN; j++)
                    acc[i][j] = fmaf(ar[i], br[j], acc[i][j]);
        }
        __syncthreads();
    }

#pragma unroll
    for (int i = 0; i < TM; i++) {
        float* cp = C + (size_t)(bm + ty*TM + i) * ldc + bn + tx*TN;
#pragma unroll
        for (int j = 0; j < TN; j += 4) {
            float4 v = make_float4(acc[i][j], acc[i][j+1], acc[i][j+2], acc[i][j+3]);
            *(float4*)(cp + j) = v;
        }
    }
}

// ---------------- elementwise: silu / rope ----------------
__global__ void silu_qnope_k() {
    int i = blockIdx.x * blockDim.x + threadIdx.x;
    if (i >= MROWS * NH * DN) return;
    int m = i >> 11;              // / (16*128)
    int r = i & 2047;
    int h = r >> 7;
    int d = r & 127;
    size_t idx = (size_t)m * QW + h * 192 + d;
    g_q[idx] = silu_f(g_q[idx]);
}

__global__ void rope_silu_qpe_k(const float* __restrict__ fc) {
    int i = blockIdx.x * blockDim.x + threadIdx.x;
    if (i >= MROWS * NH * (DRD/2)) return;
    int m = i >> 9;               // / (16*32)
    int r = i & 511;
    int h = r >> 5;
    int p = r & 31;
    int s = m & (SEQ - 1);
    float c = fc[s*64 + p*2 + 0];
    float sn = fc[s*64 + p*2 + 1];
    size_t base = (size_t)m * QW + h * 192 + DN + 2*p;
    float xr = g_q[base], xi = g_q[base+1];
    float yr = xr*c - xi*sn;
    float yi = xr*sn + xi*c;
    g_q[base]   = silu_f(yr);
    g_q[base+1] = silu_f(yi);
}

__global__ void silu_k_k() {
    int i = blockIdx.x * blockDim.x + threadIdx.x;
    if (i >= MROWS * NH * DN) return;
    int m = i >> 11;
    int r = i & 2047;
    int h = r >> 7;
    int d = r & 127;
    size_t idx = (size_t)m * KVBW + h * 256 + d;
    g_kvb[idx] = silu_f(g_kvb[idx]);
}

__global__ void rope_silu_kpe_k(const float* __restrict__ fc) {
    int i = blockIdx.x * blockDim.x + threadIdx.x;
    if (i >= MROWS * (DRD/2)) return;
    int m = i >> 5;
    int p = i & 31;
    int s = m & (SEQ - 1);
    float c = fc[s*64 + p*2 + 0];
    float sn = fc[s*64 + p*2 + 1];
    size_t src = (size_t)m * KVAW + KVLAT + 2*p;
    float xr = g_kva[src], xi = g_kva[src+1];
    float yr = xr*c - xi*sn;
    float yi = xr*sn + xi*c;
    g_kpe[(size_t)m*DRD + 2*p]     = silu_f(yr);
    g_kpe[(size_t)m*DRD + 2*p + 1] = silu_f(yi);
}

// ---------------- eta: per (batch, 256-seq-chunk) max, applied per head ----------------
__global__ void eta_init_k() {
    if (threadIdx.x < 256) g_eta_enc[threadIdx.x] = 0u;
}

__global__ void eta_max_k(int tensor) {
    int b = blockIdx.x >> 4;
    int c = blockIdx.x & 15;
    int nPer;
    if (tensor == 0 || tensor == 1) nPer = 256 * NH * DN;      // 524288
    else if (tensor == 2)           nPer = 256 * NH * DRD;     // 262144
    else                            nPer = 256 * DRD;          // 16384
    int per = nPer / gridDim.y;
    int start = blockIdx.y * per;
    float mx = -FLT_MAX;
    for (int e = start + threadIdx.x; e < start + per; e += blockDim.x) {
        float v;
        if (tensor == 0) {
            int sl = e >> 11; int r = e & 2047; int h = r >> 7; int d = r & 127;
            int m = b*SEQ + c*256 + sl;
            v = g_q[(size_t)m*QW + h*192 + d];
        } else if (tensor == 1) {
            int sl = e >> 11; int r = e & 2047; int h = r >> 7; int d = r & 127;
            int m = b*SEQ + c*256 + sl;
            v = g_kvb[(size_t)m*KVBW + h*256 + d];
        } else if (tensor == 2) {
            int sl = e >> 10; int r = e & 1023; int h = r >> 6; int d = r & 63;
            int m = b*SEQ + c*256 + sl;
            v = g_q[(size_t)m*QW + h*192 + DN + d];
        } else {
            int sl = e >> 6; int d = e & 63;
            int m = b*SEQ + c*256 + sl;
            v = g_kpe[(size_t)m*DRD + d];
        }
        mx = fmaxf(mx, v);
    }
    __shared__ float red[256];
    red[threadIdx.x] = mx;
    __syncthreads();
    for (int s = 128; s > 0; s >>= 1) {
        if (threadIdx.x < s) red[threadIdx.x] = fmaxf(red[threadIdx.x], red[threadIdx.x + s]);
        __syncthreads();
    }
    if (threadIdx.x == 0)
        atomicMax(&g_eta_enc[tensor*64 + blockIdx.x], encf(red[0]));
}

__global__ void eta_fin_k() {
    int i = threadIdx.x;
    if (i < 256) {
        float m = decf(g_eta_enc[i]);
        if (m == 0.0f) m = 1e-6f;
        g_eta[i] = fminf(10.0f / m, 1.0f);
    }
}

// ---------------- block attention: per (b, 64-block, h) ----------------
__global__ void __launch_bounds__(256) attn_kernel() {
    __shared__ float sA[64*65];   // q-side tiles, then scores/attn
    __shared__ float sB[64*65];   // k-side tiles, then v tiles
    int bnb = blockIdx.x;         // b*64 + n
    int h   = blockIdx.y;
    int b = bnb >> 6, n = bnb & 63;
    int m0 = b*SEQ + n*64;
    int tid = threadIdx.x;
    int ty = tid >> 4, tx = tid & 15;

    float eqn = g_eta[  0 + b*16 + h];
    float ekn = g_eta[ 64 + b*16 + h];
    float eqp = g_eta[128 + b*16 + h];
    float ekp = g_eta[192 + b*16 + h];

    float c_pe[4][4], c_np[4][4];
#pragma unroll
    for (int i = 0; i < 4; i++)
#pragma unroll
        for (int j = 0; j < 4; j++) { c_pe[i][j] = 0.f; c_np[i][j] = 0.f; }

    // --- PE part: qp[64x64] x kp[64x64] ---
    for (int idx = tid; idx < 4096; idx += 256) {
        int q = idx >> 6, d = idx & 63;
        sA[d*65 + q] = g_q[(size_t)(m0+q)*QW + h*192 + DN + d];
        sB[d*65 + q] = g_kpe[(size_t)(m0+q)*DRD + d];
    }
    __syncthreads();
#pragma unroll 4
    for (int k = 0; k < 64; k++) {
        float a[4], bb[4];
#pragma unroll
        for (int i = 0; i < 4; i++) a[i]  = sA[k*65 + ty*4 + i];
#pragma unroll
        for (int j = 0; j < 4; j++) bb[j] = sB[k*65 + tx*4 + j];
#pragma unroll
        for (int i = 0; i < 4; i++)
#pragma unroll
            for (int j = 0; j < 4; j++)
                c_pe[i][j] = fmaf(a[i], bb[j], c_pe[i][j]);
    }
    __syncthreads();

    // --- NOPE part: qn[64x128] x kn[64x128] in 2 chunks ---
    for (int ch = 0; ch < 2; ch++) {
        for (int idx = tid; idx < 4096; idx += 256) {
            int q = idx >> 6, d = idx & 63;
            sA[d*65 + q] = g_q  [(size_t)(m0+q)*QW   + h*192 + ch*64 + d];
            sB[d*65 + q] = g_kvb[(size_t)(m0+q)*KVBW + h*256 + ch*64 + d];
        }
        __syncthreads();
#pragma unroll 4
        for (int k = 0; k < 64; k++) {
            float a[4], bb[4];
#pragma unroll
            for (int i = 0; i < 4; i++) a[i]  = sA[k*65 + ty*4 + i];
#pragma unroll
            for (int j = 0; j < 4; j++) bb[j] = sB[k*65 + tx*4 + j];
#pragma unroll
            for (int i = 0; i < 4; i++)
#pragma unroll
                for (int j = 0; j < 4; j++)
                    c_np[i][j] = fmaf(a[i], bb[j], c_np[i][j]);
        }
        __syncthreads();
    }

    // --- scores (into sA region), causal mask ---
    float fn = eqn * ekn * SCALE_F;
    float fp = eqp * ekp * SCALE_F;
#pragma unroll
    for (int i = 0; i < 4; i++)
#pragma unroll
        for (int j = 0; j < 4; j++) {
            int q = ty*4 + i, kk = tx*4 + j;
            float v = c_np[i][j]*fn + c_pe[i][j]*fp;
            if (kk > q) v = -3.402823466e38f;
            sA[q*65 + kk] = v;
        }
    __syncthreads();

    // --- softmax: 8 warps x 8 rows each ---
    {
        int w = tid >> 5, lane = tid & 31;
        for (int r = w; r < 64; r += 8) {
            float x0 = sA[r*65 + lane];
            float x1 = sA[r*65 + lane + 32];
            float mx = fmaxf(x0, x1);
#pragma unroll
            for (int o = 16; o > 0; o >>= 1)
                mx = fmaxf(mx, __shfl_xor_sync(0xffffffffu, mx, o));
            float e0 = expf(x0 - mx);
            float e1 = expf(x1 - mx);
            float sm = e0 + e1;
#pragma unroll
            for (int o = 16; o > 0; o >>= 1)
                sm += __shfl_xor_sync(0xffffffffu, sm, o);
            float inv = 1.0f / sm;
            sA[r*65 + lane]      = e0 * inv;
            sA[r*65 + lane + 32] = e1 * inv;
        }
    }
    __syncthreads();

    // --- out = attn @ v, DV=128 in 2 chunks of 64 ---
    for (int ch = 0; ch < 2; ch++) {
        for (int idx = tid; idx < 4096; idx += 256) {
            int kk = idx >> 6, d = idx & 63;
            sB[kk*65 + d] = g_kvb[(size_t)(m0+kk)*KVBW + h*256 + DN + ch*64 + d];
        }
        __syncthreads();
        float o[4][4];
#pragma unroll
        for (int i = 0; i < 4; i++)
#pragma unroll
            for (int j = 0; j < 4; j++) o[i][j] = 0.f;
#pragma unroll 4
        for (int k = 0; k < 64; k++) {
            float a[4], bb[4];
#pragma unroll
            for (int i = 0; i < 4; i++) a[i]  = sA[(ty*4 + i)*65 + k];
#pragma unroll
            for (int j = 0; j < 4; j++) bb[j] = sB[k*65 + tx*4 + j];
#pragma unroll
            for (int i = 0; i < 4; i++)
#pragma unroll
                for (int j = 0; j < 4; j++)
                    o[i][j] = fmaf(a[i], bb[j], o[i][j]);
        }
#pragma unroll
        for (int i = 0; i < 4; i++) {
            float4 v = make_float4(o[i][0], o[i][1], o[i][2], o[i][3]);
            *(float4*)&g_attn[(size_t)(m0 + ty*4 + i)*OW + h*DVD + ch*64 + tx*4] = v;
        }
        __syncthreads();
    }
}

// ---------------- launch ----------------
extern "C" void kernel_launch(void* const* d_in, const int* in_sizes, int n_in,
                              void* d_out, int out_size)
{
    const float* x     = (const float*)d_in[0];
    const float* fc    = (const float*)d_in[1];
    const float* wq_a  = (const float*)d_in[2];
    const float* wq_b  = (const float*)d_in[3];
    const float* wkv_a = (const float*)d_in[4];
    const float* wkv_b = (const float*)d_in[5];
    const float* wo    = (const float*)d_in[6];
    float* out = (float*)d_out;

    float *qlat, *q, *kva, *kvb, *attn;
    cudaGetSymbolAddress((void**)&qlat, g_qlat);
    cudaGetSymbolAddress((void**)&q,    g_q);
    cudaGetSymbolAddress((void**)&kva,  g_kva);
    cudaGetSymbolAddress((void**)&kvb,  g_kvb);
    cudaGetSymbolAddress((void**)&attn, g_attn);

    // 1) q_lat = x @ wq_a^T          [16384,512]  K=2048
    sgemm_nt<128,8><<<dim3(QLAT/128, MROWS/128), 256>>>(x, wq_a, qlat, DMODEL, DMODEL, DMODEL, QLAT);
    // 2) q = q_lat @ wq_b^T          [16384,3072] K=512
    sgemm_nt<128,8><<<dim3(QW/128, MROWS/128), 256>>>(qlat, wq_b, q, QLAT, QLAT, QLAT, QW);
    // 3) kv_a = x @ wkv_a^T          [16384,576]  K=2048
    sgemm_nt<64,4><<<dim3(KVAW/64, MROWS/128), 256>>>(x, wkv_a, kva, DMODEL, DMODEL, DMODEL, KVAW);
    // 4) kvb = kv_a[:, :512] @ wkv_b^T  [16384,4096] K=512
    sgemm_nt<128,8><<<dim3(KVBW/128, MROWS/128), 256>>>(kva, wkv_b, kvb, KVLAT, KVAW, KVLAT, KVBW);

    // 5) activations / rope
    silu_qnope_k   <<<(MROWS*NH*DN)/256, 256>>>();
    rope_silu_qpe_k<<<(MROWS*NH*32)/256, 256>>>(fc);
    silu_k_k       <<<(MROWS*NH*DN)/256, 256>>>();
    rope_silu_kpe_k<<<(MROWS*32)/256, 256>>>(fc);

    // 6) eta
    eta_init_k<<<1, 256>>>();
    eta_max_k<<<dim3(64, 8), 256>>>(0);
    eta_max_k<<<dim3(64, 8), 256>>>(1);
    eta_max_k<<<dim3(64, 4), 256>>>(2);
    eta_max_k<<<dim3(64, 1), 256>>>(3);
    eta_fin_k<<<1, 256>>>();

    // 7) block attention
    attn_kernel<<<dim3(BQ*64, NH), 256>>>();

    // 8) out = attn_out @ wo^T       [16384,2048] K=2048
    sgemm_nt<128,8><<<dim3(DMODEL/128, MROWS/128), 256>>>(attn, wo, out, OW, OW, OW, DMODEL);
}

// round 3
// speedup vs baseline: 2.3091x; 2.3091x over previous
#include <cuda_runtime.h>
#include <cuda_bf16.h>
#include <math.h>
#include <float.h>
#include <stdint.h>

// Problem constants
#define BQ      4
#define SEQ     4096
#define DMODEL  2048
#define NH      16
#define DN      128
#define DRD     64
#define DVD     128
#define QLAT    512
#define KVLAT   512
#define MROWS   (BQ*SEQ)          // 16384
#define QW      (NH*(DN+DRD))     // 3072
#define KVAW    (KVLAT+DRD)       // 576
#define KVBW    (NH*(DN+DVD))     // 4096
#define OW      (NH*DVD)          // 2048
#define SCALE_F 0.07216878364870323f   // (128+64)^-0.5

// ---------------- scratch (device globals; no allocation allowed) ----------------
__device__ float g_qlat[MROWS*QLAT];
__device__ float g_q   [MROWS*QW];
__device__ float g_kva [MROWS*KVAW];
__device__ float g_kvb [MROWS*KVBW];
__device__ float g_kpe [MROWS*DRD];
__device__ float g_attn[MROWS*OW];
__device__ unsigned int g_eta_enc[256];
__device__ float g_eta[256];

// ---------------- helpers ----------------
__device__ __forceinline__ float silu_f(float x) { return x / (1.0f + expf(-x)); }

__device__ __forceinline__ unsigned encf(float f) {
    unsigned u = __float_as_uint(f);
    return (u & 0x80000000u) ? ~u : (u | 0x80000000u);
}
__device__ __forceinline__ float decf(unsigned u) {
    return (u & 0x80000000u) ? __uint_as_float(u ^ 0x80000000u) : __uint_as_float(~u);
}

__device__ __forceinline__ uint32_t smem_u32(const void* p) {
    uint32_t a;
    asm("{ .reg .u64 t; cvta.to.shared.u64 t, %1; cvt.u32.u64 %0, t; }" : "=r"(a) : "l"(p));
    return a;
}
__device__ __forceinline__ void cpasync16(uint32_t dst, const void* src, bool pred) {
    int sz = pred ? 16 : 0;
    asm volatile("cp.async.cg.shared.global [%0], [%1], 16, %2;" :: "r"(dst), "l"(src), "r"(sz));
}
__device__ __forceinline__ void cp_commit() { asm volatile("cp.async.commit_group;" ::: "memory"); }
__device__ __forceinline__ void cp_wait1()  { asm volatile("cp.async.wait_group 1;"  ::: "memory"); }

__device__ __forceinline__ uint32_t f2tf(float f) {
    uint32_t r;
    asm("cvt.rna.tf32.f32 %0, %1;" : "=r"(r) : "f"(f));
    return r;
}
__device__ __forceinline__ void mma8(float* d, const uint32_t* a, const uint32_t* b) {
    asm volatile("mma.sync.aligned.m16n8k8.row.col.f32.tf32.tf32.f32 "
        "{%0,%1,%2,%3},{%4,%5,%6,%7},{%8,%9},{%0,%1,%2,%3};"
        : "+f"(d[0]), "+f"(d[1]), "+f"(d[2]), "+f"(d[3])
        : "r"(a[0]), "r"(a[1]), "r"(a[2]), "r"(a[3]), "r"(b[0]), "r"(b[1]));
}

// ---------------- tf32 mma.sync GEMM: C[M,N] = A[M,K] @ B[N,K]^T ----------------
// BM=BN=128, BK=32, 256 threads (8 warps, each 32x64), 3-stage cp.async pipeline.
#define SSTR 36
#define STAGE_F (128*SSTR)              // floats per operand per stage
#define GEMM_SMEM (3*2*STAGE_F*4)       // 110592 bytes

__global__ void __launch_bounds__(256)
gemm_tf32(const float* __restrict__ A, const float* __restrict__ B, float* __restrict__ C,
          int N, int K, int lda, int ldb)
{
    extern __shared__ float sm[];
    float* AsB = sm;                    // 3 stages A
    float* BsB = sm + 3*STAGE_F;        // 3 stages B

    int tid  = threadIdx.x;
    int bm   = blockIdx.y * 128;
    int bn   = blockIdx.x * 128;
    int wid  = tid >> 5, lane = tid & 31;
    int wm   = (wid >> 1) * 32;
    int wn   = (wid & 1) * 64;
    int lr   = lane >> 2, lc = lane & 3;

    float acc[2][8][4];
#pragma unroll
    for (int t = 0; t < 2; t++)
#pragma unroll
        for (int j = 0; j < 8; j++)
#pragma unroll
            for (int v = 0; v < 4; v++) acc[t][j][v] = 0.f;

    auto loadStage = [&](int s, int ko) {
        float* as = AsB + s * STAGE_F;
        float* bs = BsB + s * STAGE_F;
#pragma unroll
        for (int j = 0; j < 4; j++) {
            int idx = j * 256 + tid;
            int r = idx >> 3, kq = idx & 7;
            cpasync16(smem_u32(as + r * SSTR + kq * 4),
                      A + (size_t)(bm + r) * lda + ko + kq * 4, true);
        }
#pragma unroll
        for (int j = 0; j < 4; j++) {
            int idx = j * 256 + tid;
            int r = idx >> 3, kq = idx & 7;
            bool p = (bn + r) < N;
            cpasync16(smem_u32(bs + r * SSTR + kq * 4),
                      B + (size_t)(p ? (bn + r) : 0) * ldb + ko + kq * 4, p);
        }
    };

    int nk = K / 32;
    loadStage(0, 0);  cp_commit();
    loadStage(1, 32); cp_commit();

    for (int i = 0; i < nk; i++) {
        int s = i % 3;
        cp_wait1();
        __syncthreads();
        if (i + 2 < nk) loadStage((i + 2) % 3, (i + 2) * 32);
        cp_commit();

        const float* as = AsB + s * STAGE_F;
        const float* bs = BsB + s * STAGE_F;
#pragma unroll
        for (int ks = 0; ks < 4; ks++) {
            int k0 = ks * 8;
            uint32_t af[2][4], bf[8][2];
#pragma unroll
            for (int t = 0; t < 2; t++) {
                int r0 = wm + t * 16 + lr;
                af[t][0] = f2tf(as[(r0    ) * SSTR + k0 + lc    ]);
                af[t][1] = f2tf(as[(r0 + 8) * SSTR + k0 + lc    ]);
                af[t][2] = f2tf(as[(r0    ) * SSTR + k0 + lc + 4]);
                af[t][3] = f2tf(as[(r0 + 8) * SSTR + k0 + lc + 4]);
            }
#pragma unroll
            for (int j = 0; j < 8; j++) {
                int c0 = wn + j * 8 + lr;
                bf[j][0] = f2tf(bs[c0 * SSTR + k0 + lc    ]);
                bf[j][1] = f2tf(bs[c0 * SSTR + k0 + lc + 4]);
            }
#pragma unroll
            for (int t = 0; t < 2; t++)
#pragma unroll
                for (int j = 0; j < 8; j++)
                    mma8(acc[t][j], af[t], bf[j]);
        }
    }

    // epilogue: fp32 stores
#pragma unroll
    for (int t = 0; t < 2; t++) {
        int row = bm + wm + t * 16 + lr;
#pragma unroll
        for (int j = 0; j < 8; j++) {
            int col = bn + wn + j * 8 + lc * 2;
            if (col < N) {
                float2 v0 = make_float2(acc[t][j][0], acc[t][j][1]);
                float2 v1 = make_float2(acc[t][j][2], acc[t][j][3]);
                *(float2*)&C[(size_t)row * N + col]       = v0;
                *(float2*)&C[(size_t)(row + 8) * N + col] = v1;
            }
        }
    }
}

// ---------------- elementwise: silu / rope ----------------
__global__ void silu_qnope_k() {
    int i = blockIdx.x * blockDim.x + threadIdx.x;
    if (i >= MROWS * NH * DN) return;
    int m = i >> 11;
    int r = i & 2047;
    int h = r >> 7;
    int d = r & 127;
    size_t idx = (size_t)m * QW + h * 192 + d;
    g_q[idx] = silu_f(g_q[idx]);
}

__global__ void rope_silu_qpe_k(const float* __restrict__ fc) {
    int i = blockIdx.x * blockDim.x + threadIdx.x;
    if (i >= MROWS * NH * (DRD/2)) return;
    int m = i >> 9;
    int r = i & 511;
    int h = r >> 5;
    int p = r & 31;
    int s = m & (SEQ - 1);
    float c = fc[s*64 + p*2 + 0];
    float sn = fc[s*64 + p*2 + 1];
    size_t base = (size_t)m * QW + h * 192 + DN + 2*p;
    float xr = g_q[base], xi = g_q[base+1];
    float yr = xr*c - xi*sn;
    float yi = xr*sn + xi*c;
    g_q[base]   = silu_f(yr);
    g_q[base+1] = silu_f(yi);
}

__global__ void silu_k_k() {
    int i = blockIdx.x * blockDim.x + threadIdx.x;
    if (i >= MROWS * NH * DN) return;
    int m = i >> 11;
    int r = i & 2047;
    int h = r >> 7;
    int d = r & 127;
    size_t idx = (size_t)m * KVBW + h * 256 + d;
    g_kvb[idx] = silu_f(g_kvb[idx]);
}

__global__ void rope_silu_kpe_k(const float* __restrict__ fc) {
    int i = blockIdx.x * blockDim.x + threadIdx.x;
    if (i >= MROWS * (DRD/2)) return;
    int m = i >> 5;
    int p = i & 31;
    int s = m & (SEQ - 1);
    float c = fc[s*64 + p*2 + 0];
    float sn = fc[s*64 + p*2 + 1];
    size_t src = (size_t)m * KVAW + KVLAT + 2*p;
    float xr = g_kva[src], xi = g_kva[src+1];
    float yr = xr*c - xi*sn;
    float yi = xr*sn + xi*c;
    g_kpe[(size_t)m*DRD + 2*p]     = silu_f(yr);
    g_kpe[(size_t)m*DRD + 2*p + 1] = silu_f(yi);
}

// ---------------- eta ----------------
__global__ void eta_init_k() {
    if (threadIdx.x < 256) g_eta_enc[threadIdx.x] = 0u;
}

__global__ void eta_max_k(int tensor) {
    int b = blockIdx.x >> 4;
    int c = blockIdx.x & 15;
    int nPer;
    if (tensor == 0 || tensor == 1) nPer = 256 * NH * DN;
    else if (tensor == 2)           nPer = 256 * NH * DRD;
    else                            nPer = 256 * DRD;
    int per = nPer / gridDim.y;
    int start = blockIdx.y * per;
    float mx = -FLT_MAX;
    for (int e = start + threadIdx.x; e < start + per; e += blockDim.x) {
        float v;
        if (tensor == 0) {
            int sl = e >> 11; int r = e & 2047; int h = r >> 7; int d = r & 127;
            int m = b*SEQ + c*256 + sl;
            v = g_q[(size_t)m*QW + h*192 + d];
        } else if (tensor == 1) {
            int sl = e >> 11; int r = e & 2047; int h = r >> 7; int d = r & 127;
            int m = b*SEQ + c*256 + sl;
            v = g_kvb[(size_t)m*KVBW + h*256 + d];
        } else if (tensor == 2) {
            int sl = e >> 10; int r = e & 1023; int h = r >> 6; int d = r & 63;
            int m = b*SEQ + c*256 + sl;
            v = g_q[(size_t)m*QW + h*192 + DN + d];
        } else {
            int sl = e >> 6; int d = e & 63;
            int m = b*SEQ + c*256 + sl;
            v = g_kpe[(size_t)m*DRD + d];
        }
        mx = fmaxf(mx, v);
    }
    __shared__ float red[256];
    red[threadIdx.x] = mx;
    __syncthreads();
    for (int s = 128; s > 0; s >>= 1) {
        if (threadIdx.x < s) red[threadIdx.x] = fmaxf(red[threadIdx.x], red[threadIdx.x + s]);
        __syncthreads();
    }
    if (threadIdx.x == 0)
        atomicMax(&g_eta_enc[tensor*64 + blockIdx.x], encf(red[0]));
}

__global__ void eta_fin_k() {
    int i = threadIdx.x;
    if (i < 256) {
        float m = decf(g_eta_enc[i]);
        if (m == 0.0f) m = 1e-6f;
        g_eta[i] = fminf(10.0f / m, 1.0f);
    }
}

// ---------------- block attention ----------------
__global__ void __launch_bounds__(256) attn_kernel() {
    __shared__ float sA[64*65];
    __shared__ float sB[64*65];
    int bnb = blockIdx.x;
    int h   = blockIdx.y;
    int b = bnb >> 6, n = bnb & 63;
    int m0 = b*SEQ + n*64;
    int tid = threadIdx.x;
    int ty = tid >> 4, tx = tid & 15;

    float eqn = g_eta[  0 + b*16 + h];
    float ekn = g_eta[ 64 + b*16 + h];
    float eqp = g_eta[128 + b*16 + h];
    float ekp = g_eta[192 + b*16 + h];

    float c_pe[4][4], c_np[4][4];
#pragma unroll
    for (int i = 0; i < 4; i++)
#pragma unroll
        for (int j = 0; j < 4; j++) { c_pe[i][j] = 0.f; c_np[i][j] = 0.f; }

    for (int idx = tid; idx < 4096; idx += 256) {
        int q = idx >> 6, d = idx & 63;
        sA[d*65 + q] = g_q[(size_t)(m0+q)*QW + h*192 + DN + d];
        sB[d*65 + q] = g_kpe[(size_t)(m0+q)*DRD + d];
    }
    __syncthreads();
#pragma unroll 4
    for (int k = 0; k < 64; k++) {
        float a[4], bb[4];
#pragma unroll
        for (int i = 0; i < 4; i++) a[i]  = sA[k*65 + ty*4 + i];
#pragma unroll
        for (int j = 0; j < 4; j++) bb[j] = sB[k*65 + tx*4 + j];
#pragma unroll
        for (int i = 0; i < 4; i++)
#pragma unroll
            for (int j = 0; j < 4; j++)
                c_pe[i][j] = fmaf(a[i], bb[j], c_pe[i][j]);
    }
    __syncthreads();

    for (int ch = 0; ch < 2; ch++) {
        for (int idx = tid; idx < 4096; idx += 256) {
            int q = idx >> 6, d = idx & 63;
            sA[d*65 + q] = g_q  [(size_t)(m0+q)*QW   + h*192 + ch*64 + d];
            sB[d*65 + q] = g_kvb[(size_t)(m0+q)*KVBW + h*256 + ch*64 + d];
        }
        __syncthreads();
#pragma unroll 4
        for (int k = 0; k < 64; k++) {
            float a[4], bb[4];
#pragma unroll
            for (int i = 0; i < 4; i++) a[i]  = sA[k*65 + ty*4 + i];
#pragma unroll
            for (int j = 0; j < 4; j++) bb[j] = sB[k*65 + tx*4 + j];
#pragma unroll
            for (int i = 0; i < 4; i++)
#pragma unroll
                for (int j = 0; j < 4; j++)
                    c_np[i][j] = fmaf(a[i], bb[j], c_np[i][j]);
        }
        __syncthreads();
    }

    float fn = eqn * ekn * SCALE_F;
    float fp = eqp * ekp * SCALE_F;
#pragma unroll
    for (int i = 0; i < 4; i++)
#pragma unroll
        for (int j = 0; j < 4; j++) {
            int q = ty*4 + i, kk = tx*4 + j;
            float v = c_np[i][j]*fn + c_pe[i][j]*fp;
            if (kk > q) v = -3.402823466e38f;
            sA[q*65 + kk] = v;
        }
    __syncthreads();

    {
        int w = tid >> 5, lane = tid & 31;
        for (int r = w; r < 64; r += 8) {
            float x0 = sA[r*65 + lane];
            float x1 = sA[r*65 + lane + 32];
            float mx = fmaxf(x0, x1);
#pragma unroll
            for (int o = 16; o > 0; o >>= 1)
                mx = fmaxf(mx, __shfl_xor_sync(0xffffffffu, mx, o));
            float e0 = expf(x0 - mx);
            float e1 = expf(x1 - mx);
            float sm = e0 + e1;
#pragma unroll
            for (int o = 16; o > 0; o >>= 1)
                sm += __shfl_xor_sync(0xffffffffu, sm, o);
            float inv = 1.0f / sm;
            sA[r*65 + lane]      = e0 * inv;
            sA[r*65 + lane + 32] = e1 * inv;
        }
    }
    __syncthreads();

    for (int ch = 0; ch < 2; ch++) {
        for (int idx = tid; idx < 4096; idx += 256) {
            int kk = idx >> 6, d = idx & 63;
            sB[kk*65 + d] = g_kvb[(size_t)(m0+kk)*KVBW + h*256 + DN + ch*64 + d];
        }
        __syncthreads();
        float o[4][4];
#pragma unroll
        for (int i = 0; i < 4; i++)
#pragma unroll
            for (int j = 0; j < 4; j++) o[i][j] = 0.f;
#pragma unroll 4
        for (int k = 0; k < 64; k++) {
            float a[4], bb[4];
#pragma unroll
            for (int i = 0; i < 4; i++) a[i]  = sA[(ty*4 + i)*65 + k];
#pragma unroll
            for (int j = 0; j < 4; j++) bb[j] = sB[k*65 + tx*4 + j];
#pragma unroll
            for (int i = 0; i < 4; i++)
#pragma unroll
                for (int j = 0; j < 4; j++)
                    o[i][j] = fmaf(a[i], bb[j], o[i][j]);
        }
#pragma unroll
        for (int i = 0; i < 4; i++) {
            float4 v = make_float4(o[i][0], o[i][1], o[i][2], o[i][3]);
            *(float4*)&g_attn[(size_t)(m0 + ty*4 + i)*OW + h*DVD + ch*64 + tx*4] = v;
        }
        __syncthreads();
    }
}

// ---------------- launch ----------------
extern "C" void kernel_launch(void* const* d_in, const int* in_sizes, int n_in,
                              void* d_out, int out_size)
{
    const float* x     = (const float*)d_in[0];
    const float* fc    = (const float*)d_in[1];
    const float* wq_a  = (const float*)d_in[2];
    const float* wq_b  = (const float*)d_in[3];
    const float* wkv_a = (const float*)d_in[4];
    const float* wkv_b = (const float*)d_in[5];
    const float* wo    = (const float*)d_in[6];
    float* out = (float*)d_out;

    float *qlat, *q, *kva, *kvb, *attn;
    cudaGetSymbolAddress((void**)&qlat, g_qlat);
    cudaGetSymbolAddress((void**)&q,    g_q);
    cudaGetSymbolAddress((void**)&kva,  g_kva);
    cudaGetSymbolAddress((void**)&kvb,  g_kvb);
    cudaGetSymbolAddress((void**)&attn, g_attn);

    cudaFuncSetAttribute(gemm_tf32, cudaFuncAttributeMaxDynamicSharedMemorySize, GEMM_SMEM);

    // 1) q_lat = x @ wq_a^T          [16384,512]  K=2048
    gemm_tf32<<<dim3(4, 128), 256, GEMM_SMEM>>>(x, wq_a, qlat, QLAT, DMODEL, DMODEL, DMODEL);
    // 2) q = q_lat @ wq_b^T          [16384,3072] K=512
    gemm_tf32<<<dim3(24, 128), 256, GEMM_SMEM>>>(qlat, wq_b, q, QW, QLAT, QLAT, QLAT);
    // 3) kv_a = x @ wkv_a^T          [16384,576]  K=2048   (N=576 -> 5 col-blocks)
    gemm_tf32<<<dim3(5, 128), 256, GEMM_SMEM>>>(x, wkv_a, kva, KVAW, DMODEL, DMODEL, DMODEL);
    // 4) kvb = kv_c @ wkv_b^T        [16384,4096] K=512    (A = kva with lda=576)
    gemm_tf32<<<dim3(32, 128), 256, GEMM_SMEM>>>(kva, wkv_b, kvb, KVBW, KVLAT, KVAW, KVLAT);

    // 5) activations / rope
    silu_qnope_k   <<<(MROWS*NH*DN)/256, 256>>>();
    rope_silu_qpe_k<<<(MROWS*NH*32)/256, 256>>>(fc);
    silu_k_k       <<<(MROWS*NH*DN)/256, 256>>>();
    rope_silu_kpe_k<<<(MROWS*32)/256, 256>>>(fc);

    // 6) eta
    eta_init_k<<<1, 256>>>();
    eta_max_k<<<dim3(64, 8), 256>>>(0);
    eta_max_k<<<dim3(64, 8), 256>>>(1);
    eta_max_k<<<dim3(64, 4), 256>>>(2);
    eta_max_k<<<dim3(64, 1), 256>>>(3);
    eta_fin_k<<<1, 256>>>();

    // 7) block attention
    attn_kernel<<<dim3(BQ*64, NH), 256>>>();

    // 8) out = attn_out @ wo^T       [16384,2048] K=2048
    gemm_tf32<<<dim3(16, 128), 256, GEMM_SMEM>>>(attn, wo, out, DMODEL, OW, OW, OW);
}

// round 4
// speedup vs baseline: 2.7332x; 1.1837x over previous
#include <cuda_runtime.h>
#include <cuda_bf16.h>
#include <math.h>
#include <float.h>
#include <stdint.h>

// Problem constants
#define BQ      4
#define SEQ     4096
#define DMODEL  2048
#define NH      16
#define DN      128
#define DRD     64
#define DVD     128
#define QLAT    512
#define KVLAT   512
#define MROWS   (BQ*SEQ)          // 16384
#define QW      (NH*(DN+DRD))     // 3072
#define KVAW    (KVLAT+DRD)       // 576
#define KVBW    (NH*(DN+DVD))     // 4096
#define OW      (NH*DVD)          // 2048
#define SCALE_F 0.07216878364870323f   // (128+64)^-0.5

// ---------------- scratch (device globals; no allocation allowed) ----------------
__device__ float g_qlat[MROWS*QLAT];
__device__ float g_q   [MROWS*QW];
__device__ float g_kva [MROWS*KVAW];
__device__ float g_kvb [MROWS*KVBW];
__device__ float g_kpe [MROWS*DRD];
__device__ float g_attn[MROWS*OW];
__device__ unsigned int g_eta_enc[256];
__device__ float g_eta[256];
// tf32-rounded copies of GEMM inputs
__device__ float g_xt  [MROWS*DMODEL];
__device__ float g_wqat[QLAT*DMODEL];
__device__ float g_wqbt[QW*QLAT];
__device__ float g_wkat[KVAW*DMODEL];
__device__ float g_wkbt[KVBW*KVLAT];
__device__ float g_wot [DMODEL*OW];

// ---------------- helpers ----------------
__device__ __forceinline__ float silu_f(float x) { return x / (1.0f + expf(-x)); }

__device__ __forceinline__ unsigned encf(float f) {
    unsigned u = __float_as_uint(f);
    return (u & 0x80000000u) ? ~u : (u | 0x80000000u);
}
__device__ __forceinline__ float decf(unsigned u) {
    return (u & 0x80000000u) ? __uint_as_float(u ^ 0x80000000u) : __uint_as_float(~u);
}

__device__ __forceinline__ uint32_t smem_u32(const void* p) {
    uint32_t a;
    asm("{ .reg .u64 t; cvta.to.shared.u64 t, %1; cvt.u32.u64 %0, t; }" : "=r"(a) : "l"(p));
    return a;
}
__device__ __forceinline__ void cpasync16(uint32_t dst, const void* src, bool pred) {
    int sz = pred ? 16 : 0;
    asm volatile("cp.async.cg.shared.global [%0], [%1], 16, %2;" :: "r"(dst), "l"(src), "r"(sz));
}
__device__ __forceinline__ void cp_commit() { asm volatile("cp.async.commit_group;" ::: "memory"); }
__device__ __forceinline__ void cp_wait1()  { asm volatile("cp.async.wait_group 1;"  ::: "memory"); }

__device__ __forceinline__ uint32_t f2tf(float f) {
    uint32_t r;
    asm("cvt.rna.tf32.f32 %0, %1;" : "=r"(r) : "f"(f));
    return r;
}
__device__ __forceinline__ void mma8(float* d, const uint32_t* a, const uint32_t* b) {
    asm volatile("mma.sync.aligned.m16n8k8.row.col.f32.tf32.tf32.f32 "
        "{%0,%1,%2,%3},{%4,%5,%6,%7},{%8,%9},{%0,%1,%2,%3};"
        : "+f"(d[0]), "+f"(d[1]), "+f"(d[2]), "+f"(d[3])
        : "r"(a[0]), "r"(a[1]), "r"(a[2]), "r"(a[3]), "r"(b[0]), "r"(b[1]));
}

// ---------------- tf32 mma.sync GEMM: C[M,N] = A[M,K] @ B[N,K]^T ----------------
// Inputs already tf32-rounded. BM=BN=128, BK=32, 256 threads, 2-stage pipeline,
// 2 CTAs/SM. Optionally rounds output to tf32 (for buffers feeding later GEMMs).
#define SSTR 36
#define STAGE_F (128*SSTR)
#define GEMM_SMEM (2*2*STAGE_F*4)      // 73728 bytes

template<bool ROUND>
__global__ void __launch_bounds__(256, 2)
gemm_tf32(const float* __restrict__ A, const float* __restrict__ B, float* __restrict__ C,
          int N, int K, int lda, int ldb)
{
    extern __shared__ float sm[];
    float* AsB = sm;
    float* BsB = sm + 2*STAGE_F;

    int tid  = threadIdx.x;
    int bm   = blockIdx.y * 128;
    int bn   = blockIdx.x * 128;
    int wid  = tid >> 5, lane = tid & 31;
    int wm   = (wid >> 1) * 32;
    int wn   = (wid & 1) * 64;
    int lr   = lane >> 2, lc = lane & 3;

    float acc[2][8][4];
#pragma unroll
    for (int t = 0; t < 2; t++)
#pragma unroll
        for (int j = 0; j < 8; j++)
#pragma unroll
            for (int v = 0; v < 4; v++) acc[t][j][v] = 0.f;

    auto loadStage = [&](int s, int ko) {
        float* as = AsB + s * STAGE_F;
        float* bs = BsB + s * STAGE_F;
#pragma unroll
        for (int j = 0; j < 4; j++) {
            int idx = j * 256 + tid;
            int r = idx >> 3, kq = idx & 7;
            cpasync16(smem_u32(as + r * SSTR + kq * 4),
                      A + (size_t)(bm + r) * lda + ko + kq * 4, true);
        }
#pragma unroll
        for (int j = 0; j < 4; j++) {
            int idx = j * 256 + tid;
            int r = idx >> 3, kq = idx & 7;
            bool p = (bn + r) < N;
            cpasync16(smem_u32(bs + r * SSTR + kq * 4),
                      B + (size_t)(p ? (bn + r) : 0) * ldb + ko + kq * 4, p);
        }
    };

    int nk = K / 32;
    loadStage(0, 0); cp_commit();

    for (int i = 0; i < nk; i++) {
        int s = i & 1;
        if (i + 1 < nk) loadStage((i + 1) & 1, (i + 1) * 32);
        cp_commit();
        cp_wait1();
        __syncthreads();

        const float* as = AsB + s * STAGE_F;
        const float* bs = BsB + s * STAGE_F;
#pragma unroll
        for (int ks = 0; ks < 4; ks++) {
            int k0 = ks * 8;
            uint32_t af[2][4], bf[8][2];
#pragma unroll
            for (int t = 0; t < 2; t++) {
                int r0 = wm + t * 16 + lr;
                af[t][0] = __float_as_uint(as[(r0    ) * SSTR + k0 + lc    ]);
                af[t][1] = __float_as_uint(as[(r0 + 8) * SSTR + k0 + lc    ]);
                af[t][2] = __float_as_uint(as[(r0    ) * SSTR + k0 + lc + 4]);
                af[t][3] = __float_as_uint(as[(r0 + 8) * SSTR + k0 + lc + 4]);
            }
#pragma unroll
            for (int j = 0; j < 8; j++) {
                int c0 = wn + j * 8 + lr;
                bf[j][0] = __float_as_uint(bs[c0 * SSTR + k0 + lc    ]);
                bf[j][1] = __float_as_uint(bs[c0 * SSTR + k0 + lc + 4]);
            }
#pragma unroll
            for (int t = 0; t < 2; t++)
#pragma unroll
                for (int j = 0; j < 8; j++)
                    mma8(acc[t][j], af[t], bf[j]);
        }
        __syncthreads();
    }

#pragma unroll
    for (int t = 0; t < 2; t++) {
        int row = bm + wm + t * 16 + lr;
#pragma unroll
        for (int j = 0; j < 8; j++) {
            int col = bn + wn + j * 8 + lc * 2;
            if (col < N) {
                float v[4];
#pragma unroll
                for (int q = 0; q < 4; q++)
                    v[q] = ROUND ? __uint_as_float(f2tf(acc[t][j][q])) : acc[t][j][q];
                *(float2*)&C[(size_t)row * N + col]       = make_float2(v[0], v[1]);
                *(float2*)&C[(size_t)(row + 8) * N + col] = make_float2(v[2], v[3]);
            }
        }
    }
}

// ---------------- tf32 pre-round ----------------
__global__ void round_tf32_k(const float* __restrict__ src, float* __restrict__ dst, int n4) {
    int i = blockIdx.x * blockDim.x + threadIdx.x;
    if (i >= n4) return;
    float4 v = ((const float4*)src)[i];
    v.x = __uint_as_float(f2tf(v.x));
    v.y = __uint_as_float(f2tf(v.y));
    v.z = __uint_as_float(f2tf(v.z));
    v.w = __uint_as_float(f2tf(v.w));
    ((float4*)dst)[i] = v;
}

// ---------------- elementwise: silu / rope ----------------
__global__ void silu_qnope_k() {
    int i = blockIdx.x * blockDim.x + threadIdx.x;
    if (i >= MROWS * NH * DN) return;
    int m = i >> 11;
    int r = i & 2047;
    int h = r >> 7;
    int d = r & 127;
    size_t idx = (size_t)m * QW + h * 192 + d;
    g_q[idx] = silu_f(g_q[idx]);
}

__global__ void rope_silu_qpe_k(const float* __restrict__ fc) {
    int i = blockIdx.x * blockDim.x + threadIdx.x;
    if (i >= MROWS * NH * (DRD/2)) return;
    int m = i >> 9;
    int r = i & 511;
    int h = r >> 5;
    int p = r & 31;
    int s = m & (SEQ - 1);
    float c = fc[s*64 + p*2 + 0];
    float sn = fc[s*64 + p*2 + 1];
    size_t base = (size_t)m * QW + h * 192 + DN + 2*p;
    float xr = g_q[base], xi = g_q[base+1];
    float yr = xr*c - xi*sn;
    float yi = xr*sn + xi*c;
    g_q[base]   = silu_f(yr);
    g_q[base+1] = silu_f(yi);
}

__global__ void silu_k_k() {
    int i = blockIdx.x * blockDim.x + threadIdx.x;
    if (i >= MROWS * NH * DN) return;
    int m = i >> 11;
    int r = i & 2047;
    int h = r >> 7;
    int d = r & 127;
    size_t idx = (size_t)m * KVBW + h * 256 + d;
    g_kvb[idx] = silu_f(g_kvb[idx]);
}

__global__ void rope_silu_kpe_k(const float* __restrict__ fc) {
    int i = blockIdx.x * blockDim.x + threadIdx.x;
    if (i >= MROWS * (DRD/2)) return;
    int m = i >> 5;
    int p = i & 31;
    int s = m & (SEQ - 1);
    float c = fc[s*64 + p*2 + 0];
    float sn = fc[s*64 + p*2 + 1];
    size_t src = (size_t)m * KVAW + KVLAT + 2*p;
    float xr = g_kva[src], xi = g_kva[src+1];
    float yr = xr*c - xi*sn;
    float yi = xr*sn + xi*c;
    g_kpe[(size_t)m*DRD + 2*p]     = silu_f(yr);
    g_kpe[(size_t)m*DRD + 2*p + 1] = silu_f(yi);
}

// ---------------- eta ----------------
__global__ void eta_init_k() {
    if (threadIdx.x < 256) g_eta_enc[threadIdx.x] = 0u;
}

__global__ void eta_max_k(int tensor) {
    int b = blockIdx.x >> 4;
    int c = blockIdx.x & 15;
    int nPer;
    if (tensor == 0 || tensor == 1) nPer = 256 * NH * DN;
    else if (tensor == 2)           nPer = 256 * NH * DRD;
    else                            nPer = 256 * DRD;
    int per = nPer / gridDim.y;
    int start = blockIdx.y * per;
    float mx = -FLT_MAX;
    for (int e = start + threadIdx.x; e < start + per; e += blockDim.x) {
        float v;
        if (tensor == 0) {
            int sl = e >> 11; int r = e & 2047; int h = r >> 7; int d = r & 127;
            int m = b*SEQ + c*256 + sl;
            v = g_q[(size_t)m*QW + h*192 + d];
        } else if (tensor == 1) {
            int sl = e >> 11; int r = e & 2047; int h = r >> 7; int d = r & 127;
            int m = b*SEQ + c*256 + sl;
            v = g_kvb[(size_t)m*KVBW + h*256 + d];
        } else if (tensor == 2) {
            int sl = e >> 10; int r = e & 1023; int h = r >> 6; int d = r & 63;
            int m = b*SEQ + c*256 + sl;
            v = g_q[(size_t)m*QW + h*192 + DN + d];
        } else {
            int sl = e >> 6; int d = e & 63;
            int m = b*SEQ + c*256 + sl;
            v = g_kpe[(size_t)m*DRD + d];
        }
        mx = fmaxf(mx, v);
    }
    __shared__ float red[256];
    red[threadIdx.x] = mx;
    __syncthreads();
    for (int s = 128; s > 0; s >>= 1) {
        if (threadIdx.x < s) red[threadIdx.x] = fmaxf(red[threadIdx.x], red[threadIdx.x + s]);
        __syncthreads();
    }
    if (threadIdx.x == 0)
        atomicMax(&g_eta_enc[tensor*64 + blockIdx.x], encf(red[0]));
}

__global__ void eta_fin_k() {
    int i = threadIdx.x;
    if (i < 256) {
        float m = decf(g_eta_enc[i]);
        if (m == 0.0f) m = 1e-6f;
        g_eta[i] = fminf(10.0f / m, 1.0f);
    }
}

// ---------------- block attention ----------------
__global__ void __launch_bounds__(256) attn_kernel() {
    __shared__ float sA[64*65];
    __shared__ float sB[64*65];
    int bnb = blockIdx.x;
    int h   = blockIdx.y;
    int b = bnb >> 6, n = bnb & 63;
    int m0 = b*SEQ + n*64;
    int tid = threadIdx.x;
    int ty = tid >> 4, tx = tid & 15;

    float eqn = g_eta[  0 + b*16 + h];
    float ekn = g_eta[ 64 + b*16 + h];
    float eqp = g_eta[128 + b*16 + h];
    float ekp = g_eta[192 + b*16 + h];

    float c_pe[4][4], c_np[4][4];
#pragma unroll
    for (int i = 0; i < 4; i++)
#pragma unroll
        for (int j = 0; j < 4; j++) { c_pe[i][j] = 0.f; c_np[i][j] = 0.f; }

    for (int idx = tid; idx < 4096; idx += 256) {
        int q = idx >> 6, d = idx & 63;
        sA[d*65 + q] = g_q[(size_t)(m0+q)*QW + h*192 + DN + d];
        sB[d*65 + q] = g_kpe[(size_t)(m0+q)*DRD + d];
    }
    __syncthreads();
#pragma unroll 4
    for (int k = 0; k < 64; k++) {
        float a[4], bb[4];
#pragma unroll
        for (int i = 0; i < 4; i++) a[i]  = sA[k*65 + ty*4 + i];
#pragma unroll
        for (int j = 0; j < 4; j++) bb[j] = sB[k*65 + tx*4 + j];
#pragma unroll
        for (int i = 0; i < 4; i++)
#pragma unroll
            for (int j = 0; j < 4; j++)
                c_pe[i][j] = fmaf(a[i], bb[j], c_pe[i][j]);
    }
    __syncthreads();

    for (int ch = 0; ch < 2; ch++) {
        for (int idx = tid; idx < 4096; idx += 256) {
            int q = idx >> 6, d = idx & 63;
            sA[d*65 + q] = g_q  [(size_t)(m0+q)*QW   + h*192 + ch*64 + d];
            sB[d*65 + q] = g_kvb[(size_t)(m0+q)*KVBW + h*256 + ch*64 + d];
        }
        __syncthreads();
#pragma unroll 4
        for (int k = 0; k < 64; k++) {
            float a[4], bb[4];
#pragma unroll
            for (int i = 0; i < 4; i++) a[i]  = sA[k*65 + ty*4 + i];
#pragma unroll
            for (int j = 0; j < 4; j++) bb[j] = sB[k*65 + tx*4 + j];
#pragma unroll
            for (int i = 0; i < 4; i++)
#pragma unroll
                for (int j = 0; j < 4; j++)
                    c_np[i][j] = fmaf(a[i], bb[j], c_np[i][j]);
        }
        __syncthreads();
    }

    float fn = eqn * ekn * SCALE_F;
    float fp = eqp * ekp * SCALE_F;
#pragma unroll
    for (int i = 0; i < 4; i++)
#pragma unroll
        for (int j = 0; j < 4; j++) {
            int q = ty*4 + i, kk = tx*4 + j;
            float v = c_np[i][j]*fn + c_pe[i][j]*fp;
            if (kk > q) v = -3.402823466e38f;
            sA[q*65 + kk] = v;
        }
    __syncthreads();

    {
        int w = tid >> 5, lane = tid & 31;
        for (int r = w; r < 64; r += 8) {
            float x0 = sA[r*65 + lane];
            float x1 = sA[r*65 + lane + 32];
            float mx = fmaxf(x0, x1);
#pragma unroll
            for (int o = 16; o > 0; o >>= 1)
                mx = fmaxf(mx, __shfl_xor_sync(0xffffffffu, mx, o));
            float e0 = expf(x0 - mx);
            float e1 = expf(x1 - mx);
            float sm = e0 + e1;
#pragma unroll
            for (int o = 16; o > 0; o >>= 1)
                sm += __shfl_xor_sync(0xffffffffu, sm, o);
            float inv = 1.0f / sm;
            sA[r*65 + lane]      = e0 * inv;
            sA[r*65 + lane + 32] = e1 * inv;
        }
    }
    __syncthreads();

    for (int ch = 0; ch < 2; ch++) {
        for (int idx = tid; idx < 4096; idx += 256) {
            int kk = idx >> 6, d = idx & 63;
            sB[kk*65 + d] = g_kvb[(size_t)(m0+kk)*KVBW + h*256 + DN + ch*64 + d];
        }
        __syncthreads();
        float o[4][4];
#pragma unroll
        for (int i = 0; i < 4; i++)
#pragma unroll
            for (int j = 0; j < 4; j++) o[i][j] = 0.f;
#pragma unroll 4
        for (int k = 0; k < 64; k++) {
            float a[4], bb[4];
#pragma unroll
            for (int i = 0; i < 4; i++) a[i]  = sA[(ty*4 + i)*65 + k];
#pragma unroll
            for (int j = 0; j < 4; j++) bb[j] = sB[k*65 + tx*4 + j];
#pragma unroll
            for (int i = 0; i < 4; i++)
#pragma unroll
                for (int j = 0; j < 4; j++)
                    o[i][j] = fmaf(a[i], bb[j], o[i][j]);
        }
        // store rounded to tf32: g_attn feeds GEMM5's A operand
#pragma unroll
        for (int i = 0; i < 4; i++) {
            float4 v = make_float4(__uint_as_float(f2tf(o[i][0])), __uint_as_float(f2tf(o[i][1])),
                                   __uint_as_float(f2tf(o[i][2])), __uint_as_float(f2tf(o[i][3])));
            *(float4*)&g_attn[(size_t)(m0 + ty*4 + i)*OW + h*DVD + ch*64 + tx*4] = v;
        }
        __syncthreads();
    }
}

// ---------------- launch ----------------
extern "C" void kernel_launch(void* const* d_in, const int* in_sizes, int n_in,
                              void* d_out, int out_size)
{
    const float* x     = (const float*)d_in[0];
    const float* fc    = (const float*)d_in[1];
    const float* wq_a  = (const float*)d_in[2];
    const float* wq_b  = (const float*)d_in[3];
    const float* wkv_a = (const float*)d_in[4];
    const float* wkv_b = (const float*)d_in[5];
    const float* wo    = (const float*)d_in[6];
    float* out = (float*)d_out;

    float *qlat, *q, *kva, *kvb, *attn;
    float *xt, *wqat, *wqbt, *wkat, *wkbt, *wot;
    cudaGetSymbolAddress((void**)&qlat, g_qlat);
    cudaGetSymbolAddress((void**)&q,    g_q);
    cudaGetSymbolAddress((void**)&kva,  g_kva);
    cudaGetSymbolAddress((void**)&kvb,  g_kvb);
    cudaGetSymbolAddress((void**)&attn, g_attn);
    cudaGetSymbolAddress((void**)&xt,   g_xt);
    cudaGetSymbolAddress((void**)&wqat, g_wqat);
    cudaGetSymbolAddress((void**)&wqbt, g_wqbt);
    cudaGetSymbolAddress((void**)&wkat, g_wkat);
    cudaGetSymbolAddress((void**)&wkbt, g_wkbt);
    cudaGetSymbolAddress((void**)&wot,  g_wot);

    cudaFuncSetAttribute(gemm_tf32<true>,  cudaFuncAttributeMaxDynamicSharedMemorySize, GEMM_SMEM);
    cudaFuncSetAttribute(gemm_tf32<false>, cudaFuncAttributeMaxDynamicSharedMemorySize, GEMM_SMEM);

    // 0) pre-round GEMM inputs to tf32
    auto rnd = [](const float* s, float* d, int n) {
        round_tf32_k<<<(n/4 + 255)/256, 256>>>(s, d, n/4);
    };
    rnd(x,     xt,   MROWS*DMODEL);
    rnd(wq_a,  wqat, QLAT*DMODEL);
    rnd(wq_b,  wqbt, QW*QLAT);
    rnd(wkv_a, wkat, KVAW*DMODEL);
    rnd(wkv_b, wkbt, KVBW*KVLAT);
    rnd(wo,    wot,  DMODEL*OW);

    // 1) q_lat = x @ wq_a^T          [16384,512]  K=2048  (round: feeds GEMM2 A)
    gemm_tf32<true ><<<dim3(4, 128), 256, GEMM_SMEM>>>(xt, wqat, qlat, QLAT, DMODEL, DMODEL, DMODEL);
    // 2) q = q_lat @ wq_b^T          [16384,3072] K=512
    gemm_tf32<false><<<dim3(24, 128), 256, GEMM_SMEM>>>(qlat, wqbt, q, QW, QLAT, QLAT, QLAT);
    // 3) kv_a = x @ wkv_a^T          [16384,576]  K=2048  (round: cols<512 feed GEMM4 A)
    gemm_tf32<true ><<<dim3(5, 128), 256, GEMM_SMEM>>>(xt, wkat, kva, KVAW, DMODEL, DMODEL, DMODEL);
    // 4) kvb = kv_c @ wkv_b^T        [16384,4096] K=512
    gemm_tf32<false><<<dim3(32, 128), 256, GEMM_SMEM>>>(kva, wkbt, kvb, KVBW, KVLAT, KVAW, KVLAT);

    // 5) activations / rope
    silu_qnope_k   <<<(MROWS*NH*DN)/256, 256>>>();
    rope_silu_qpe_k<<<(MROWS*NH*32)/256, 256>>>(fc);
    silu_k_k       <<<(MROWS*NH*DN)/256, 256>>>();
    rope_silu_kpe_k<<<(MROWS*32)/256, 256>>>(fc);

    // 6) eta
    eta_init_k<<<1, 256>>>();
    eta_max_k<<<dim3(64, 8), 256>>>(0);
    eta_max_k<<<dim3(64, 8), 256>>>(1);
    eta_max_k<<<dim3(64, 4), 256>>>(2);
    eta_max_k<<<dim3(64, 1), 256>>>(3);
    eta_fin_k<<<1, 256>>>();

    // 7) block attention (stores tf32-rounded g_attn)
    attn_kernel<<<dim3(BQ*64, NH), 256>>>();

    // 8) out = attn_out @ wo^T       [16384,2048] K=2048
    gemm_tf32<false><<<dim3(16, 128), 256, GEMM_SMEM>>>(attn, wot, out, DMODEL, OW, OW, OW);
}

// round 5
// speedup vs baseline: 2.8444x; 1.0407x over previous
#include <cuda_runtime.h>
#include <cuda_bf16.h>
#include <math.h>
#include <float.h>
#include <stdint.h>

// Problem constants
#define BQ      4
#define SEQ     4096
#define DMODEL  2048
#define NH      16
#define DN      128
#define DRD     64
#define DVD     128
#define QLAT    512
#define KVLAT   512
#define MROWS   (BQ*SEQ)          // 16384
#define QW      (NH*(DN+DRD))     // 3072
#define KVAW    (KVLAT+DRD)       // 576
#define KVBW    (NH*(DN+DVD))     // 4096
#define OW      (NH*DVD)          // 2048
#define SCALE_F 0.07216878364870323f   // (128+64)^-0.5

// ---------------- scratch ----------------
__device__ float g_qlat[MROWS*QLAT];
__device__ float g_q   [MROWS*QW];
__device__ float g_kva [MROWS*KVAW];
__device__ float g_kvb [MROWS*KVBW];
__device__ float g_kpe [MROWS*DRD];
__device__ float g_attn[MROWS*OW];
__device__ unsigned int g_eta_enc[256];
__device__ float g_eta[256];
__device__ float g_xt  [MROWS*DMODEL];
__device__ float g_wqat[QLAT*DMODEL];
__device__ float g_wqbt[QW*QLAT];
__device__ float g_wkat[KVAW*DMODEL];
__device__ float g_wkbt[KVBW*KVLAT];
__device__ float g_wot [DMODEL*OW];

// ---------------- helpers ----------------
__device__ __forceinline__ float silu_f(float x) { return x / (1.0f + expf(-x)); }

__device__ __forceinline__ unsigned encf(float f) {
    unsigned u = __float_as_uint(f);
    return (u & 0x80000000u) ? ~u : (u | 0x80000000u);
}
__device__ __forceinline__ float decf(unsigned u) {
    return (u & 0x80000000u) ? __uint_as_float(u ^ 0x80000000u) : __uint_as_float(~u);
}

__device__ __forceinline__ uint32_t smem_u32(const void* p) {
    uint32_t a;
    asm("{ .reg .u64 t; cvta.to.shared.u64 t, %1; cvt.u32.u64 %0, t; }" : "=r"(a) : "l"(p));
    return a;
}
__device__ __forceinline__ void cpasync16(uint32_t dst, const void* src, bool pred) {
    int sz = pred ? 16 : 0;
    asm volatile("cp.async.cg.shared.global [%0], [%1], 16, %2;" :: "r"(dst), "l"(src), "r"(sz));
}
__device__ __forceinline__ void cp_commit() { asm volatile("cp.async.commit_group;" ::: "memory"); }
__device__ __forceinline__ void cp_wait1()  { asm volatile("cp.async.wait_group 1;"  ::: "memory"); }

__device__ __forceinline__ uint32_t f2tf(float f) {
    uint32_t r;
    asm("cvt.rna.tf32.f32 %0, %1;" : "=r"(r) : "f"(f));
    return r;
}
__device__ __forceinline__ void mma8(float* d, const uint32_t* a, const uint32_t* b) {
    asm volatile("mma.sync.aligned.m16n8k8.row.col.f32.tf32.tf32.f32 "
        "{%0,%1,%2,%3},{%4,%5,%6,%7},{%8,%9},{%0,%1,%2,%3};"
        : "+f"(d[0]), "+f"(d[1]), "+f"(d[2]), "+f"(d[3])
        : "r"(a[0]), "r"(a[1]), "r"(a[2]), "r"(a[3]), "r"(b[0]), "r"(b[1]));
}

// ---------------- tf32 mma.sync GEMM: C[M,N] = A[M,K] @ B[N,K]^T ----------------
// EPI: 0=plain, 1=round-to-tf32, 2=Q epilogue (silu/rope, stride 192),
//      3=KVB epilogue (silu on d<128, stride 256)
#define SSTR 36
#define STAGE_F (128*SSTR)
#define GEMM_SMEM (3*2*STAGE_F*4)      // 110592 bytes

template<int EPI>
__global__ void __launch_bounds__(256, 2)
gemm_tf32(const float* __restrict__ A, const float* __restrict__ B, float* __restrict__ C,
          int N, int K, int lda, int ldb, const float* __restrict__ fc)
{
    extern __shared__ float sm[];
    float* AsB = sm;
    float* BsB = sm + 3*STAGE_F;

    int tid  = threadIdx.x;
    int bm   = blockIdx.y * 128;
    int bn   = blockIdx.x * 128;
    int wid  = tid >> 5, lane = tid & 31;
    int wm   = (wid >> 1) * 32;
    int wn   = (wid & 1) * 64;
    int lr   = lane >> 2, lc = lane & 3;

    float acc[2][8][4];
#pragma unroll
    for (int t = 0; t < 2; t++)
#pragma unroll
        for (int j = 0; j < 8; j++)
#pragma unroll
            for (int v = 0; v < 4; v++) acc[t][j][v] = 0.f;

    auto loadStage = [&](int s, int ko) {
        float* as = AsB + s * STAGE_F;
        float* bs = BsB + s * STAGE_F;
#pragma unroll
        for (int j = 0; j < 4; j++) {
            int idx = j * 256 + tid;
            int r = idx >> 3, kq = idx & 7;
            cpasync16(smem_u32(as + r * SSTR + kq * 4),
                      A + (size_t)(bm + r) * lda + ko + kq * 4, true);
        }
#pragma unroll
        for (int j = 0; j < 4; j++) {
            int idx = j * 256 + tid;
            int r = idx >> 3, kq = idx & 7;
            bool p = (bn + r) < N;
            cpasync16(smem_u32(bs + r * SSTR + kq * 4),
                      B + (size_t)(p ? (bn + r) : 0) * ldb + ko + kq * 4, p);
        }
    };

    int nk = K / 32;
    loadStage(0, 0);  cp_commit();
    loadStage(1, 32); cp_commit();

    for (int i = 0; i < nk; i++) {
        int s = i % 3;
        cp_wait1();
        __syncthreads();
        if (i + 2 < nk) loadStage((i + 2) % 3, (i + 2) * 32);
        cp_commit();

        const float* as = AsB + s * STAGE_F;
        const float* bs = BsB + s * STAGE_F;
#pragma unroll
        for (int ks = 0; ks < 4; ks++) {
            int k0 = ks * 8;
            uint32_t af[2][4], bf[8][2];
#pragma unroll
            for (int t = 0; t < 2; t++) {
                int r0 = wm + t * 16 + lr;
                af[t][0] = __float_as_uint(as[(r0    ) * SSTR + k0 + lc    ]);
                af[t][1] = __float_as_uint(as[(r0 + 8) * SSTR + k0 + lc    ]);
                af[t][2] = __float_as_uint(as[(r0    ) * SSTR + k0 + lc + 4]);
                af[t][3] = __float_as_uint(as[(r0 + 8) * SSTR + k0 + lc + 4]);
            }
#pragma unroll
            for (int j = 0; j < 8; j++) {
                int c0 = wn + j * 8 + lr;
                bf[j][0] = __float_as_uint(bs[c0 * SSTR + k0 + lc    ]);
                bf[j][1] = __float_as_uint(bs[c0 * SSTR + k0 + lc + 4]);
            }
#pragma unroll
            for (int t = 0; t < 2; t++)
#pragma unroll
                for (int j = 0; j < 8; j++)
                    mma8(acc[t][j], af[t], bf[j]);
        }
    }

    // epilogue
#pragma unroll
    for (int t = 0; t < 2; t++) {
        int row0 = bm + wm + t * 16 + lr;
#pragma unroll
        for (int j = 0; j < 8; j++) {
            int col = bn + wn + j * 8 + lc * 2;
            if (col < N) {
                float v[4] = {acc[t][j][0], acc[t][j][1], acc[t][j][2], acc[t][j][3]};
                if (EPI == 1) {
#pragma unroll
                    for (int q = 0; q < 4; q++) v[q] = __uint_as_float(f2tf(v[q]));
                } else if (EPI == 2) {
                    int d = col % 192;
                    if (d < DN) {
#pragma unroll
                        for (int q = 0; q < 4; q++) v[q] = silu_f(v[q]);
                    } else {
                        int p = (d - DN) >> 1;
#pragma unroll
                        for (int half = 0; half < 2; half++) {
                            int srow = (row0 + half * 8) & (SEQ - 1);
                            float cs = fc[srow*64 + p*2], sn = fc[srow*64 + p*2 + 1];
                            float xr = v[half*2], xi = v[half*2+1];
                            v[half*2]   = silu_f(xr*cs - xi*sn);
                            v[half*2+1] = silu_f(xr*sn + xi*cs);
                        }
                    }
                } else if (EPI == 3) {
                    int d = col % 256;
                    if (d < DN) {
#pragma unroll
                        for (int q = 0; q < 4; q++) v[q] = silu_f(v[q]);
                    }
                }
                *(float2*)&C[(size_t)row0 * N + col]       = make_float2(v[0], v[1]);
                *(float2*)&C[(size_t)(row0 + 8) * N + col] = make_float2(v[2], v[3]);
            }
        }
    }
}

// ---------------- tf32 pre-round ----------------
__global__ void round_tf32_k(const float* __restrict__ src, float* __restrict__ dst, int n4) {
    int i = blockIdx.x * blockDim.x + threadIdx.x;
    if (i >= n4) return;
    float4 v = ((const float4*)src)[i];
    v.x = __uint_as_float(f2tf(v.x));
    v.y = __uint_as_float(f2tf(v.y));
    v.z = __uint_as_float(f2tf(v.z));
    v.w = __uint_as_float(f2tf(v.w));
    ((float4*)dst)[i] = v;
}

// ---------------- rope+silu for k_pe (from g_kva cols 512..575) ----------------
__global__ void rope_silu_kpe_k(const float* __restrict__ fc) {
    int i = blockIdx.x * blockDim.x + threadIdx.x;
    if (i >= MROWS * (DRD/2)) return;
    int m = i >> 5;
    int p = i & 31;
    int s = m & (SEQ - 1);
    float c = fc[s*64 + p*2 + 0];
    float sn = fc[s*64 + p*2 + 1];
    size_t src = (size_t)m * KVAW + KVLAT + 2*p;
    float xr = g_kva[src], xi = g_kva[src+1];
    float yr = xr*c - xi*sn;
    float yi = xr*sn + xi*c;
    g_kpe[(size_t)m*DRD + 2*p]     = silu_f(yr);
    g_kpe[(size_t)m*DRD + 2*p + 1] = silu_f(yi);
}

// ---------------- eta ----------------
__global__ void eta_init_k() {
    if (threadIdx.x < 256) g_eta_enc[threadIdx.x] = 0u;
}

__global__ void eta_max_k(int tensor) {
    int b = blockIdx.x >> 4;
    int c = blockIdx.x & 15;
    int nPer;
    if (tensor == 0 || tensor == 1) nPer = 256 * NH * DN;
    else if (tensor == 2)           nPer = 256 * NH * DRD;
    else                            nPer = 256 * DRD;
    int per = nPer / gridDim.y;
    int start = blockIdx.y * per;
    float mx = -FLT_MAX;
    for (int e = start + threadIdx.x; e < start + per; e += blockDim.x) {
        float v;
        if (tensor == 0) {
            int sl = e >> 11; int r = e & 2047; int h = r >> 7; int d = r & 127;
            int m = b*SEQ + c*256 + sl;
            v = g_q[(size_t)m*QW + h*192 + d];
        } else if (tensor == 1) {
            int sl = e >> 11; int r = e & 2047; int h = r >> 7; int d = r & 127;
            int m = b*SEQ + c*256 + sl;
            v = g_kvb[(size_t)m*KVBW + h*256 + d];
        } else if (tensor == 2) {
            int sl = e >> 10; int r = e & 1023; int h = r >> 6; int d = r & 63;
            int m = b*SEQ + c*256 + sl;
            v = g_q[(size_t)m*QW + h*192 + DN + d];
        } else {
            int sl = e >> 6; int d = e & 63;
            int m = b*SEQ + c*256 + sl;
            v = g_kpe[(size_t)m*DRD + d];
        }
        mx = fmaxf(mx, v);
    }
    __shared__ float red[256];
    red[threadIdx.x] = mx;
    __syncthreads();
    for (int s = 128; s > 0; s >>= 1) {
        if (threadIdx.x < s) red[threadIdx.x] = fmaxf(red[threadIdx.x], red[threadIdx.x + s]);
        __syncthreads();
    }
    if (threadIdx.x == 0)
        atomicMax(&g_eta_enc[tensor*64 + blockIdx.x], encf(red[0]));
}

__global__ void eta_fin_k() {
    int i = threadIdx.x;
    if (i < 256) {
        float m = decf(g_eta_enc[i]);
        if (m == 0.0f) m = 1e-6f;
        g_eta[i] = fminf(10.0f / m, 1.0f);
    }
}

// ---------------- block attention ----------------
__global__ void __launch_bounds__(256) attn_kernel() {
    __shared__ float sA[64*65];
    __shared__ float sB[64*65];
    int bnb = blockIdx.x;
    int h   = blockIdx.y;
    int b = bnb >> 6, n = bnb & 63;
    int m0 = b*SEQ + n*64;
    int tid = threadIdx.x;
    int ty = tid >> 4, tx = tid & 15;

    float eqn = g_eta[  0 + b*16 + h];
    float ekn = g_eta[ 64 + b*16 + h];
    float eqp = g_eta[128 + b*16 + h];
    float ekp = g_eta[192 + b*16 + h];

    float c_pe[4][4], c_np[4][4];
#pragma unroll
    for (int i = 0; i < 4; i++)
#pragma unroll
        for (int j = 0; j < 4; j++) { c_pe[i][j] = 0.f; c_np[i][j] = 0.f; }

    for (int idx = tid; idx < 4096; idx += 256) {
        int q = idx >> 6, d = idx & 63;
        sA[d*65 + q] = g_q[(size_t)(m0+q)*QW + h*192 + DN + d];
        sB[d*65 + q] = g_kpe[(size_t)(m0+q)*DRD + d];
    }
    __syncthreads();
#pragma unroll 4
    for (int k = 0; k < 64; k++) {
        float a[4], bb[4];
#pragma unroll
        for (int i = 0; i < 4; i++) a[i]  = sA[k*65 + ty*4 + i];
#pragma unroll
        for (int j = 0; j < 4; j++) bb[j] = sB[k*65 + tx*4 + j];
#pragma unroll
        for (int i = 0; i < 4; i++)
#pragma unroll
            for (int j = 0; j < 4; j++)
                c_pe[i][j] = fmaf(a[i], bb[j], c_pe[i][j]);
    }
    __syncthreads();

    for (int ch = 0; ch < 2; ch++) {
        for (int idx = tid; idx < 4096; idx += 256) {
            int q = idx >> 6, d = idx & 63;
            sA[d*65 + q] = g_q  [(size_t)(m0+q)*QW   + h*192 + ch*64 + d];
            sB[d*65 + q] = g_kvb[(size_t)(m0+q)*KVBW + h*256 + ch*64 + d];
        }
        __syncthreads();
#pragma unroll 4
        for (int k = 0; k < 64; k++) {
            float a[4], bb[4];
#pragma unroll
            for (int i = 0; i < 4; i++) a[i]  = sA[k*65 + ty*4 + i];
#pragma unroll
            for (int j = 0; j < 4; j++) bb[j] = sB[k*65 + tx*4 + j];
#pragma unroll
            for (int i = 0; i < 4; i++)
#pragma unroll
                for (int j = 0; j < 4; j++)
                    c_np[i][j] = fmaf(a[i], bb[j], c_np[i][j]);
        }
        __syncthreads();
    }

    float fn = eqn * ekn * SCALE_F;
    float fp = eqp * ekp * SCALE_F;
#pragma unroll
    for (int i = 0; i < 4; i++)
#pragma unroll
        for (int j = 0; j < 4; j++) {
            int q = ty*4 + i, kk = tx*4 + j;
            float v = c_np[i][j]*fn + c_pe[i][j]*fp;
            if (kk > q) v = -3.402823466e38f;
            sA[q*65 + kk] = v;
        }
    __syncthreads();

    {
        int w = tid >> 5, lane = tid & 31;
        for (int r = w; r < 64; r += 8) {
            float x0 = sA[r*65 + lane];
            float x1 = sA[r*65 + lane + 32];
            float mx = fmaxf(x0, x1);
#pragma unroll
            for (int o = 16; o > 0; o >>= 1)
                mx = fmaxf(mx, __shfl_xor_sync(0xffffffffu, mx, o));
            float e0 = expf(x0 - mx);
            float e1 = expf(x1 - mx);
            float sm = e0 + e1;
#pragma unroll
            for (int o = 16; o > 0; o >>= 1)
                sm += __shfl_xor_sync(0xffffffffu, sm, o);
            float inv = 1.0f / sm;
            sA[r*65 + lane]      = e0 * inv;
            sA[r*65 + lane + 32] = e1 * inv;
        }
    }
    __syncthreads();

    for (int ch = 0; ch < 2; ch++) {
        for (int idx = tid; idx < 4096; idx += 256) {
            int kk = idx >> 6, d = idx & 63;
            sB[kk*65 + d] = g_kvb[(size_t)(m0+kk)*KVBW + h*256 + DN + ch*64 + d];
        }
        __syncthreads();
        float o[4][4];
#pragma unroll
        for (int i = 0; i < 4; i++)
#pragma unroll
            for (int j = 0; j < 4; j++) o[i][j] = 0.f;
#pragma unroll 4
        for (int k = 0; k < 64; k++) {
            float a[4], bb[4];
#pragma unroll
            for (int i = 0; i < 4; i++) a[i]  = sA[(ty*4 + i)*65 + k];
#pragma unroll
            for (int j = 0; j < 4; j++) bb[j] = sB[k*65 + tx*4 + j];
#pragma unroll
            for (int i = 0; i < 4; i++)
#pragma unroll
                for (int j = 0; j < 4; j++)
                    o[i][j] = fmaf(a[i], bb[j], o[i][j]);
        }
        // store rounded to tf32: g_attn feeds GEMM5's A operand
#pragma unroll
        for (int i = 0; i < 4; i++) {
            float4 v = make_float4(__uint_as_float(f2tf(o[i][0])), __uint_as_float(f2tf(o[i][1])),
                                   __uint_as_float(f2tf(o[i][2])), __uint_as_float(f2tf(o[i][3])));
            *(float4*)&g_attn[(size_t)(m0 + ty*4 + i)*OW + h*DVD + ch*64 + tx*4] = v;
        }
        __syncthreads();
    }
}

// ---------------- launch ----------------
extern "C" void kernel_launch(void* const* d_in, const int* in_sizes, int n_in,
                              void* d_out, int out_size)
{
    const float* x     = (const float*)d_in[0];
    const float* fc    = (const float*)d_in[1];
    const float* wq_a  = (const float*)d_in[2];
    const float* wq_b  = (const float*)d_in[3];
    const float* wkv_a = (const float*)d_in[4];
    const float* wkv_b = (const float*)d_in[5];
    const float* wo    = (const float*)d_in[6];
    float* out = (float*)d_out;

    float *qlat, *q, *kva, *kvb, *attn;
    float *xt, *wqat, *wqbt, *wkat, *wkbt, *wot;
    cudaGetSymbolAddress((void**)&qlat, g_qlat);
    cudaGetSymbolAddress((void**)&q,    g_q);
    cudaGetSymbolAddress((void**)&kva,  g_kva);
    cudaGetSymbolAddress((void**)&kvb,  g_kvb);
    cudaGetSymbolAddress((void**)&attn, g_attn);
    cudaGetSymbolAddress((void**)&xt,   g_xt);
    cudaGetSymbolAddress((void**)&wqat, g_wqat);
    cudaGetSymbolAddress((void**)&wqbt, g_wqbt);
    cudaGetSymbolAddress((void**)&wkat, g_wkat);
    cudaGetSymbolAddress((void**)&wkbt, g_wkbt);
    cudaGetSymbolAddress((void**)&wot,  g_wot);

    cudaFuncSetAttribute(gemm_tf32<0>, cudaFuncAttributeMaxDynamicSharedMemorySize, GEMM_SMEM);
    cudaFuncSetAttribute(gemm_tf32<1>, cudaFuncAttributeMaxDynamicSharedMemorySize, GEMM_SMEM);
    cudaFuncSetAttribute(gemm_tf32<2>, cudaFuncAttributeMaxDynamicSharedMemorySize, GEMM_SMEM);
    cudaFuncSetAttribute(gemm_tf32<3>, cudaFuncAttributeMaxDynamicSharedMemorySize, GEMM_SMEM);

    auto rnd = [](const float* s, float* d, int n) {
        round_tf32_k<<<(n/4 + 255)/256, 256>>>(s, d, n/4);
    };
    // launches 0-4
    rnd(x,     xt,   MROWS*DMODEL);
    rnd(wq_a,  wqat, QLAT*DMODEL);
    rnd(wq_b,  wqbt, QW*QLAT);
    rnd(wkv_a, wkat, KVAW*DMODEL);
    rnd(wkv_b, wkbt, KVBW*KVLAT);

    // launch 5 (ncu -s 5 profiles this): q_lat = x @ wq_a^T  [16384,512] K=2048
    gemm_tf32<1><<<dim3(4, 128), 256, GEMM_SMEM>>>(xt, wqat, qlat, QLAT, DMODEL, DMODEL, DMODEL, nullptr);
    // q = q_lat @ wq_b^T  [16384,3072] K=512, fused silu+rope epilogue
    gemm_tf32<2><<<dim3(24, 128), 256, GEMM_SMEM>>>(qlat, wqbt, q, QW, QLAT, QLAT, QLAT, fc);
    // kv_a = x @ wkv_a^T  [16384,576] K=2048
    gemm_tf32<1><<<dim3(5, 128), 256, GEMM_SMEM>>>(xt, wkat, kva, KVAW, DMODEL, DMODEL, DMODEL, nullptr);
    // kvb = kv_c @ wkv_b^T  [16384,4096] K=512, fused silu epilogue
    gemm_tf32<3><<<dim3(32, 128), 256, GEMM_SMEM>>>(kva, wkbt, kvb, KVBW, KVLAT, KVAW, KVLAT, nullptr);

    rope_silu_kpe_k<<<(MROWS*32)/256, 256>>>(fc);

    eta_init_k<<<1, 256>>>();
    eta_max_k<<<dim3(64, 8), 256>>>(0);
    eta_max_k<<<dim3(64, 8), 256>>>(1);
    eta_max_k<<<dim3(64, 4), 256>>>(2);
    eta_max_k<<<dim3(64, 1), 256>>>(3);
    eta_fin_k<<<1, 256>>>();

    attn_kernel<<<dim3(BQ*64, NH), 256>>>();

    rnd(wo, wot, DMODEL*OW);
    // out = attn_out @ wo^T  [16384,2048] K=2048
    gemm_tf32<0><<<dim3(16, 128), 256, GEMM_SMEM>>>(attn, wot, out, DMODEL, OW, OW, OW, nullptr);
}

// round 6
// speedup vs baseline: 3.1977x; 1.1242x over previous
#include <cuda_runtime.h>
#include <cuda_bf16.h>
#include <math.h>
#include <float.h>
#include <stdint.h>

// Problem constants
#define BQ      4
#define SEQ     4096
#define DMODEL  2048
#define NH      16
#define DN      128
#define DRD     64
#define DVD     128
#define QLAT    512
#define KVLAT   512
#define MROWS   (BQ*SEQ)          // 16384
#define QW      (NH*(DN+DRD))     // 3072
#define KVAW    (KVLAT+DRD)       // 576
#define KVAP    640               // padded N for wkv_a pack
#define KVBW    (NH*(DN+DVD))     // 4096
#define OW      (NH*DVD)          // 2048
#define SCALE_F 0.07216878364870323f

// ---------------- scratch ----------------
__device__ float g_q   [MROWS*QW];        // row-major q (silu/rope applied)
__device__ float g_kvb [MROWS*KVBW];      // row-major kv_b (silu on k half)
__device__ float g_kpe [MROWS*DRD];       // rope+silu k_pe
__device__ float g_kperaw[MROWS*DRD];     // raw k_pe cols (pre-rope)
__device__ unsigned int g_eta_enc[256];
__device__ float g_eta[256];
// fragment-packed operands (tf32-rounded)
__device__ float g_xpk   [MROWS*DMODEL];
__device__ float g_qlatpk[MROWS*QLAT];
__device__ float g_kvapk [MROWS*KVLAT];
__device__ float g_attnpk[MROWS*OW];
__device__ float g_wqapk [QLAT*DMODEL];
__device__ float g_wqbpk [QW*QLAT];
__device__ float g_wkapk [KVAP*DMODEL];
__device__ float g_wkbpk [KVBW*KVLAT];
__device__ float g_wopk  [DMODEL*OW];

// ---------------- helpers ----------------
__device__ __forceinline__ float silu_f(float x) { return x / (1.0f + expf(-x)); }

__device__ __forceinline__ unsigned encf(float f) {
    unsigned u = __float_as_uint(f);
    return (u & 0x80000000u) ? ~u : (u | 0x80000000u);
}
__device__ __forceinline__ float decf(unsigned u) {
    return (u & 0x80000000u) ? __uint_as_float(u ^ 0x80000000u) : __uint_as_float(~u);
}
__device__ __forceinline__ uint32_t smem_u32(const void* p) {
    uint32_t a;
    asm("{ .reg .u64 t; cvta.to.shared.u64 t, %1; cvt.u32.u64 %0, t; }" : "=r"(a) : "l"(p));
    return a;
}
__device__ __forceinline__ void cpasync16(uint32_t dst, const void* src) {
    asm volatile("cp.async.cg.shared.global [%0], [%1], 16;" :: "r"(dst), "l"(src));
}
__device__ __forceinline__ void cp_commit() { asm volatile("cp.async.commit_group;" ::: "memory"); }
__device__ __forceinline__ void cp_wait1()  { asm volatile("cp.async.wait_group 1;"  ::: "memory"); }

__device__ __forceinline__ uint32_t f2tf(float f) {
    uint32_t r;
    asm("cvt.rna.tf32.f32 %0, %1;" : "=r"(r) : "f"(f));
    return r;
}
__device__ __forceinline__ float f2tff(float f) { return __uint_as_float(f2tf(f)); }

__device__ __forceinline__ void mma8(float* d, const uint32_t* a, const uint32_t* b) {
    asm volatile("mma.sync.aligned.m16n8k8.row.col.f32.tf32.tf32.f32 "
        "{%0,%1,%2,%3},{%4,%5,%6,%7},{%8,%9},{%0,%1,%2,%3};"
        : "+f"(d[0]), "+f"(d[1]), "+f"(d[2]), "+f"(d[3])
        : "r"(a[0]), "r"(a[1]), "r"(a[2]), "r"(a[3]), "r"(b[0]), "r"(b[1]));
}

// packed-A element index: m,k -> offset (Kt = K/8 tiles)
__device__ __forceinline__ size_t a_pk_idx(int m, int k, int Kt) {
    int tm = m >> 4, rr = m & 15, lr = rr & 7, hi = rr >> 3;
    int tk = k >> 3, k7 = k & 7, qk = (k7 >> 2) << 1, lc = k7 & 3;
    return ((size_t)tm * Kt + tk) * 128 + (lr * 4 + lc) * 4 + qk + hi;
}

// ---------------- pack kernels (round to tf32) ----------------
__global__ void pack_a_k(const float* __restrict__ src, float* __restrict__ dst, int Kt, int ld, int n) {
    int o = blockIdx.x * blockDim.x + threadIdx.x;
    if (o >= n) return;
    int tile = o >> 7, l4q = o & 127, l = l4q >> 2, q = l4q & 3;
    int tm = tile / Kt, tk = tile % Kt;
    int r = tm * 16 + (q & 1) * 8 + (l >> 2);
    int k = tk * 8 + (q >> 1) * 4 + (l & 3);
    dst[o] = f2tff(src[(size_t)r * ld + k]);
}

__global__ void pack_b_k(const float* __restrict__ src, float* __restrict__ dst, int Kt, int ld, int N, int n) {
    int o = blockIdx.x * blockDim.x + threadIdx.x;
    if (o >= n) return;
    int tile = o >> 6, lq = o & 63, l = lq >> 1, q = lq & 1;
    int tn = tile / Kt, tk = tile % Kt;
    int nr = tn * 8 + (l >> 2);
    int k = tk * 8 + q * 4 + (l & 3);
    dst[o] = (nr < N) ? f2tff(src[(size_t)nr * ld + k]) : 0.0f;
}

// ---------------- packed tf32 GEMM: C[M,N] = A[M,K] @ B[N,K]^T ----------------
// A, B in fragment-packed layout. BM=BN=128, BK=32, 256 thr, 3 stages, 2 CTAs/SM.
// EPI: 0=plain C     1=packed-A out (Kt=64)  2=Q silu/rope  3=kva packed + kperaw  4=kvb silu
#define STAGE_B 32768
#define GEMM_SMEM (3*STAGE_B)     // 96 KB

template<int EPI>
__global__ void __launch_bounds__(256, 2)
gemm_pk(const float* __restrict__ A, const float* __restrict__ B, float* __restrict__ C,
        float* __restrict__ C2, int N, int K, const float* __restrict__ fc)
{
    extern __shared__ float sm[];
    uint32_t sb = smem_u32(sm);
    int Kt = K >> 3;

    int tid  = threadIdx.x;
    int bm   = blockIdx.y * 128;
    int bn   = blockIdx.x * 128;
    int wid  = tid >> 5, lane = tid & 31;
    int wm   = (wid >> 1) * 32;
    int wn   = (wid & 1) * 64;
    int lr   = lane >> 2, lc = lane & 3;

    float acc[2][8][4];
#pragma unroll
    for (int t = 0; t < 2; t++)
#pragma unroll
        for (int j = 0; j < 8; j++)
#pragma unroll
            for (int v = 0; v < 4; v++) acc[t][j][v] = 0.f;

    auto loadStage = [&](int s, int ko) {
        uint32_t abase = sb + s * STAGE_B;
        uint32_t bbase = abase + 16384;
        int kt0 = ko >> 3;
#pragma unroll
        for (int j = 0; j < 4; j++) {
            int idx = j * 256 + tid;
            int tm = idx >> 7, u = idx & 127;
            const float* src = A + ((size_t)(bm / 16 + tm) * Kt + kt0) * 128 + u * 4;
            cpasync16(abase + tm * 2048 + u * 16, src);
        }
#pragma unroll
        for (int j = 0; j < 4; j++) {
            int idx = j * 256 + tid;
            int tn = idx >> 6, u = idx & 63;
            const float* src = B + ((size_t)(bn / 8 + tn) * Kt + kt0) * 64 + u * 4;
            cpasync16(bbase + tn * 1024 + u * 16, src);
        }
    };

    int nk = K / 32;
    loadStage(0, 0);  cp_commit();
    loadStage(1, 32); cp_commit();

    for (int i = 0; i < nk; i++) {
        int s = i % 3;
        cp_wait1();
        __syncthreads();
        if (i + 2 < nk) loadStage((i + 2) % 3, (i + 2) * 32);
        cp_commit();

        const float* as = sm + s * (STAGE_B/4);
        const float* bs = as + 4096;
#pragma unroll
        for (int ks = 0; ks < 4; ks++) {
            uint32_t af[2][4], bf[8][2];
#pragma unroll
            for (int t = 0; t < 2; t++) {
                float4 v = *(const float4*)(as + ((wm >> 4) + t) * 512 + ks * 128 + lane * 4);
                af[t][0] = __float_as_uint(v.x); af[t][1] = __float_as_uint(v.y);
                af[t][2] = __float_as_uint(v.z); af[t][3] = __float_as_uint(v.w);
            }
#pragma unroll
            for (int j = 0; j < 8; j++) {
                float2 v = *(const float2*)(bs + ((wn >> 3) + j) * 256 + ks * 64 + lane * 2);
                bf[j][0] = __float_as_uint(v.x); bf[j][1] = __float_as_uint(v.y);
            }
#pragma unroll
            for (int t = 0; t < 2; t++)
#pragma unroll
                for (int j = 0; j < 8; j++)
                    mma8(acc[t][j], af[t], bf[j]);
        }
    }

    // epilogue
#pragma unroll
    for (int t = 0; t < 2; t++) {
        int row0 = bm + wm + t * 16 + lr;
#pragma unroll
        for (int j = 0; j < 8; j++) {
            int col = bn + wn + j * 8 + lc * 2;
            float v0 = acc[t][j][0], v1 = acc[t][j][1], v2 = acc[t][j][2], v3 = acc[t][j][3];
            if (EPI == 0) {
                *(float2*)&C[(size_t)row0 * N + col]       = make_float2(v0, v1);
                *(float2*)&C[(size_t)(row0 + 8) * N + col] = make_float2(v2, v3);
            } else if (EPI == 1) {
                // packed-A output, Kt_out = 64
                int tm = (bm + wm + t * 16) >> 4;
                int tk = col >> 3;
                int lp = lr * 4 + ((col & 7) & 3);
                int qk = (col & 4) >> 1;
                size_t base = ((size_t)tm * 64 + tk) * 128;
                *(float2*)&C[base + lp * 4 + qk]       = make_float2(f2tff(v0), f2tff(v2));
                *(float2*)&C[base + (lp + 1) * 4 + qk] = make_float2(f2tff(v1), f2tff(v3));
            } else if (EPI == 2) {
                int d = col % 192;
                if (d < DN) {
                    v0 = silu_f(v0); v1 = silu_f(v1); v2 = silu_f(v2); v3 = silu_f(v3);
                } else {
                    int p = (d - DN) >> 1;
                    int s0 = row0 & (SEQ - 1), s1 = (row0 + 8) & (SEQ - 1);
                    float c0 = fc[s0*64 + p*2], n0 = fc[s0*64 + p*2 + 1];
                    float c1 = fc[s1*64 + p*2], n1 = fc[s1*64 + p*2 + 1];
                    float r0 = v0*c0 - v1*n0, i0 = v0*n0 + v1*c0;
                    float r1 = v2*c1 - v3*n1, i1 = v2*n1 + v3*c1;
                    v0 = silu_f(r0); v1 = silu_f(i0); v2 = silu_f(r1); v3 = silu_f(i1);
                }
                *(float2*)&C[(size_t)row0 * N + col]       = make_float2(v0, v1);
                *(float2*)&C[(size_t)(row0 + 8) * N + col] = make_float2(v2, v3);
            } else if (EPI == 3) {
                if (col < KVLAT) {
                    int tm = (bm + wm + t * 16) >> 4;
                    int tk = col >> 3;
                    int lp = lr * 4 + ((col & 7) & 3);
                    int qk = (col & 4) >> 1;
                    size_t base = ((size_t)tm * 64 + tk) * 128;
                    *(float2*)&C[base + lp * 4 + qk]       = make_float2(f2tff(v0), f2tff(v2));
                    *(float2*)&C[base + (lp + 1) * 4 + qk] = make_float2(f2tff(v1), f2tff(v3));
                } else if (col < KVAW) {
                    *(float2*)&C2[(size_t)row0 * DRD + col - KVLAT]       = make_float2(v0, v1);
                    *(float2*)&C2[(size_t)(row0 + 8) * DRD + col - KVLAT] = make_float2(v2, v3);
                }
            } else if (EPI == 4) {
                int d = col % 256;
                if (d < DN) {
                    v0 = silu_f(v0); v1 = silu_f(v1); v2 = silu_f(v2); v3 = silu_f(v3);
                }
                *(float2*)&C[(size_t)row0 * N + col]       = make_float2(v0, v1);
                *(float2*)&C[(size_t)(row0 + 8) * N + col] = make_float2(v2, v3);
            }
        }
    }
}

// ---------------- rope+silu for k_pe ----------------
__global__ void rope_silu_kpe_k(const float* __restrict__ fc) {
    int i = blockIdx.x * blockDim.x + threadIdx.x;
    if (i >= MROWS * (DRD/2)) return;
    int m = i >> 5;
    int p = i & 31;
    int s = m & (SEQ - 1);
    float c = fc[s*64 + p*2 + 0];
    float sn = fc[s*64 + p*2 + 1];
    float xr = g_kperaw[(size_t)m*DRD + 2*p];
    float xi = g_kperaw[(size_t)m*DRD + 2*p + 1];
    float yr = xr*c - xi*sn;
    float yi = xr*sn + xi*c;
    g_kpe[(size_t)m*DRD + 2*p]     = silu_f(yr);
    g_kpe[(size_t)m*DRD + 2*p + 1] = silu_f(yi);
}

// ---------------- eta ----------------
__global__ void eta_init_k() {
    if (threadIdx.x < 256) g_eta_enc[threadIdx.x] = 0u;
}

__global__ void eta_max_k(int tensor) {
    int b = blockIdx.x >> 4;
    int c = blockIdx.x & 15;
    int nPer;
    if (tensor == 0 || tensor == 1) nPer = 256 * NH * DN;
    else if (tensor == 2)           nPer = 256 * NH * DRD;
    else                            nPer = 256 * DRD;
    int per = nPer / gridDim.y;
    int start = blockIdx.y * per;
    float mx = -FLT_MAX;
    for (int e = start + threadIdx.x; e < start + per; e += blockDim.x) {
        float v;
        if (tensor == 0) {
            int sl = e >> 11; int r = e & 2047; int h = r >> 7; int d = r & 127;
            int m = b*SEQ + c*256 + sl;
            v = g_q[(size_t)m*QW + h*192 + d];
        } else if (tensor == 1) {
            int sl = e >> 11; int r = e & 2047; int h = r >> 7; int d = r & 127;
            int m = b*SEQ + c*256 + sl;
            v = g_kvb[(size_t)m*KVBW + h*256 + d];
        } else if (tensor == 2) {
            int sl = e >> 10; int r = e & 1023; int h = r >> 6; int d = r & 63;
            int m = b*SEQ + c*256 + sl;
            v = g_q[(size_t)m*QW + h*192 + DN + d];
        } else {
            int sl = e >> 6; int d = e & 63;
            int m = b*SEQ + c*256 + sl;
            v = g_kpe[(size_t)m*DRD + d];
        }
        mx = fmaxf(mx, v);
    }
    __shared__ float red[256];
    red[threadIdx.x] = mx;
    __syncthreads();
    for (int s = 128; s > 0; s >>= 1) {
        if (threadIdx.x < s) red[threadIdx.x] = fmaxf(red[threadIdx.x], red[threadIdx.x + s]);
        __syncthreads();
    }
    if (threadIdx.x == 0)
        atomicMax(&g_eta_enc[tensor*64 + blockIdx.x], encf(red[0]));
}

__global__ void eta_fin_k() {
    int i = threadIdx.x;
    if (i < 256) {
        float m = decf(g_eta_enc[i]);
        if (m == 0.0f) m = 1e-6f;
        g_eta[i] = fminf(10.0f / m, 1.0f);
    }
}

// ---------------- block attention (output packed for GEMM5 A) ----------------
__global__ void __launch_bounds__(256) attn_kernel() {
    __shared__ float sA[64*65];
    __shared__ float sB[64*65];
    int bnb = blockIdx.x;
    int h   = blockIdx.y;
    int b = bnb >> 6, n = bnb & 63;
    int m0 = b*SEQ + n*64;
    int tid = threadIdx.x;
    int ty = tid >> 4, tx = tid & 15;

    float eqn = g_eta[  0 + b*16 + h];
    float ekn = g_eta[ 64 + b*16 + h];
    float eqp = g_eta[128 + b*16 + h];
    float ekp = g_eta[192 + b*16 + h];

    float c_pe[4][4], c_np[4][4];
#pragma unroll
    for (int i = 0; i < 4; i++)
#pragma unroll
        for (int j = 0; j < 4; j++) { c_pe[i][j] = 0.f; c_np[i][j] = 0.f; }

    for (int idx = tid; idx < 4096; idx += 256) {
        int q = idx >> 6, d = idx & 63;
        sA[d*65 + q] = g_q[(size_t)(m0+q)*QW + h*192 + DN + d];
        sB[d*65 + q] = g_kpe[(size_t)(m0+q)*DRD + d];
    }
    __syncthreads();
#pragma unroll 4
    for (int k = 0; k < 64; k++) {
        float a[4], bb[4];
#pragma unroll
        for (int i = 0; i < 4; i++) a[i]  = sA[k*65 + ty*4 + i];
#pragma unroll
        for (int j = 0; j < 4; j++) bb[j] = sB[k*65 + tx*4 + j];
#pragma unroll
        for (int i = 0; i < 4; i++)
#pragma unroll
            for (int j = 0; j < 4; j++)
                c_pe[i][j] = fmaf(a[i], bb[j], c_pe[i][j]);
    }
    __syncthreads();

    for (int ch = 0; ch < 2; ch++) {
        for (int idx = tid; idx < 4096; idx += 256) {
            int q = idx >> 6, d = idx & 63;
            sA[d*65 + q] = g_q  [(size_t)(m0+q)*QW   + h*192 + ch*64 + d];
            sB[d*65 + q] = g_kvb[(size_t)(m0+q)*KVBW + h*256 + ch*64 + d];
        }
        __syncthreads();
#pragma unroll 4
        for (int k = 0; k < 64; k++) {
            float a[4], bb[4];
#pragma unroll
            for (int i = 0; i < 4; i++) a[i]  = sA[k*65 + ty*4 + i];
#pragma unroll
            for (int j = 0; j < 4; j++) bb[j] = sB[k*65 + tx*4 + j];
#pragma unroll
            for (int i = 0; i < 4; i++)
#pragma unroll
                for (int j = 0; j < 4; j++)
                    c_np[i][j] = fmaf(a[i], bb[j], c_np[i][j]);
        }
        __syncthreads();
    }

    float fn = eqn * ekn * SCALE_F;
    float fp = eqp * ekp * SCALE_F;
#pragma unroll
    for (int i = 0; i < 4; i++)
#pragma unroll
        for (int j = 0; j < 4; j++) {
            int q = ty*4 + i, kk = tx*4 + j;
            float v = c_np[i][j]*fn + c_pe[i][j]*fp;
            if (kk > q) v = -3.402823466e38f;
            sA[q*65 + kk] = v;
        }
    __syncthreads();

    {
        int w = tid >> 5, lane = tid & 31;
        for (int r = w; r < 64; r += 8) {
            float x0 = sA[r*65 + lane];
            float x1 = sA[r*65 + lane + 32];
            float mx = fmaxf(x0, x1);
#pragma unroll
            for (int o = 16; o > 0; o >>= 1)
                mx = fmaxf(mx, __shfl_xor_sync(0xffffffffu, mx, o));
            float e0 = expf(x0 - mx);
            float e1 = expf(x1 - mx);
            float sm = e0 + e1;
#pragma unroll
            for (int o = 16; o > 0; o >>= 1)
                sm += __shfl_xor_sync(0xffffffffu, sm, o);
            float inv = 1.0f / sm;
            sA[r*65 + lane]      = e0 * inv;
            sA[r*65 + lane + 32] = e1 * inv;
        }
    }
    __syncthreads();

    for (int ch = 0; ch < 2; ch++) {
        for (int idx = tid; idx < 4096; idx += 256) {
            int kk = idx >> 6, d = idx & 63;
            sB[kk*65 + d] = g_kvb[(size_t)(m0+kk)*KVBW + h*256 + DN + ch*64 + d];
        }
        __syncthreads();
        float o[4][4];
#pragma unroll
        for (int i = 0; i < 4; i++)
#pragma unroll
            for (int j = 0; j < 4; j++) o[i][j] = 0.f;
#pragma unroll 4
        for (int k = 0; k < 64; k++) {
            float a[4], bb[4];
#pragma unroll
            for (int i = 0; i < 4; i++) a[i]  = sA[(ty*4 + i)*65 + k];
#pragma unroll
            for (int j = 0; j < 4; j++) bb[j] = sB[k*65 + tx*4 + j];
#pragma unroll
            for (int i = 0; i < 4; i++)
#pragma unroll
                for (int j = 0; j < 4; j++)
                    o[i][j] = fmaf(a[i], bb[j], o[i][j]);
        }
        // scatter into packed-A layout for GEMM5 (Kt = 256)
#pragma unroll
        for (int i = 0; i < 4; i++) {
            int m = m0 + ty*4 + i;
            int kk0 = h*DVD + ch*64 + tx*4;
#pragma unroll
            for (int j = 0; j < 4; j++)
                g_attnpk[a_pk_idx(m, kk0 + j, 256)] = f2tff(o[i][j]);
        }
        __syncthreads();
    }
}

// ---------------- launch ----------------
extern "C" void kernel_launch(void* const* d_in, const int* in_sizes, int n_in,
                              void* d_out, int out_size)
{
    const float* x     = (const float*)d_in[0];
    const float* fc    = (const float*)d_in[1];
    const float* wq_a  = (const float*)d_in[2];
    const float* wq_b  = (const float*)d_in[3];
    const float* wkv_a = (const float*)d_in[4];
    const float* wkv_b = (const float*)d_in[5];
    const float* wo    = (const float*)d_in[6];
    float* out = (float*)d_out;

    float *q, *kvb, *kperaw;
    float *xpk, *qlatpk, *kvapk, *attnpk;
    float *wqapk, *wqbpk, *wkapk, *wkbpk, *wopk;
    cudaGetSymbolAddress((void**)&q,      g_q);
    cudaGetSymbolAddress((void**)&kvb,    g_kvb);
    cudaGetSymbolAddress((void**)&kperaw, g_kperaw);
    cudaGetSymbolAddress((void**)&xpk,    g_xpk);
    cudaGetSymbolAddress((void**)&qlatpk, g_qlatpk);
    cudaGetSymbolAddress((void**)&kvapk,  g_kvapk);
    cudaGetSymbolAddress((void**)&attnpk, g_attnpk);
    cudaGetSymbolAddress((void**)&wqapk,  g_wqapk);
    cudaGetSymbolAddress((void**)&wqbpk,  g_wqbpk);
    cudaGetSymbolAddress((void**)&wkapk,  g_wkapk);
    cudaGetSymbolAddress((void**)&wkbpk,  g_wkbpk);
    cudaGetSymbolAddress((void**)&wopk,   g_wopk);

    cudaFuncSetAttribute(gemm_pk<0>, cudaFuncAttributeMaxDynamicSharedMemorySize, GEMM_SMEM);
    cudaFuncSetAttribute(gemm_pk<1>, cudaFuncAttributeMaxDynamicSharedMemorySize, GEMM_SMEM);
    cudaFuncSetAttribute(gemm_pk<2>, cudaFuncAttributeMaxDynamicSharedMemorySize, GEMM_SMEM);
    cudaFuncSetAttribute(gemm_pk<3>, cudaFuncAttributeMaxDynamicSharedMemorySize, GEMM_SMEM);
    cudaFuncSetAttribute(gemm_pk<4>, cudaFuncAttributeMaxDynamicSharedMemorySize, GEMM_SMEM);

    // launches 0-4: pack inputs
    pack_a_k<<<(MROWS*DMODEL)/256, 256>>>(x, xpk, DMODEL/8, DMODEL, MROWS*DMODEL);
    pack_b_k<<<(QLAT*DMODEL)/256, 256>>>(wq_a, wqapk, DMODEL/8, DMODEL, QLAT, QLAT*DMODEL);
    pack_b_k<<<(QW*QLAT)/256, 256>>>(wq_b, wqbpk, QLAT/8, QLAT, QW, QW*QLAT);
    pack_b_k<<<(KVAP*DMODEL)/256, 256>>>(wkv_a, wkapk, DMODEL/8, DMODEL, KVAW, KVAP*DMODEL);
    pack_b_k<<<(KVBW*KVLAT)/256, 256>>>(wkv_b, wkbpk, KVLAT/8, KVLAT, KVBW, KVBW*KVLAT);

    // launch 5: q_lat = x @ wq_a^T  [16384,512] K=2048 -> packed
    gemm_pk<1><<<dim3(4, 128), 256, GEMM_SMEM>>>(xpk, wqapk, qlatpk, nullptr, QLAT, DMODEL, nullptr);
    // q = q_lat @ wq_b^T  [16384,3072] K=512 -> row-major + silu/rope
    gemm_pk<2><<<dim3(24, 128), 256, GEMM_SMEM>>>(qlatpk, wqbpk, q, nullptr, QW, QLAT, fc);
    // kv_a = x @ wkv_a^T  [16384,576→640] K=2048 -> packed kv_c + raw k_pe
    gemm_pk<3><<<dim3(5, 128), 256, GEMM_SMEM>>>(xpk, wkapk, kvapk, kperaw, KVAP, DMODEL, nullptr);
    // kvb = kv_c @ wkv_b^T  [16384,4096] K=512 -> row-major + silu
    gemm_pk<4><<<dim3(32, 128), 256, GEMM_SMEM>>>(kvapk, wkbpk, kvb, nullptr, KVBW, KVLAT, nullptr);

    rope_silu_kpe_k<<<(MROWS*32)/256, 256>>>(fc);

    eta_init_k<<<1, 256>>>();
    eta_max_k<<<dim3(64, 8), 256>>>(0);
    eta_max_k<<<dim3(64, 8), 256>>>(1);
    eta_max_k<<<dim3(64, 4), 256>>>(2);
    eta_max_k<<<dim3(64, 1), 256>>>(3);
    eta_fin_k<<<1, 256>>>();

    attn_kernel<<<dim3(BQ*64, NH), 256>>>();

    pack_b_k<<<(DMODEL*OW)/256, 256>>>(wo, wopk, OW/8, OW, DMODEL, DMODEL*OW);
    // out = attn_out @ wo^T  [16384,2048] K=2048
    gemm_pk<0><<<dim3(16, 128), 256, GEMM_SMEM>>>(attnpk, wopk, out, nullptr, DMODEL, OW, nullptr);
}

// round 8
// speedup vs baseline: 3.3659x; 1.0526x over previous
#include <cuda_runtime.h>
#include <cuda_bf16.h>
#include <math.h>
#include <float.h>
#include <stdint.h>

// Problem constants
#define BQ      4
#define SEQ     4096
#define DMODEL  2048
#define NH      16
#define DN      128
#define DRD     64
#define DVD     128
#define QLAT    512
#define KVLAT   512
#define MROWS   (BQ*SEQ)          // 16384
#define QW      (NH*(DN+DRD))     // 3072
#define KVAW    (KVLAT+DRD)       // 576
#define KVAP    640               // padded N for wkv_a pack
#define KVBW    (NH*(DN+DVD))     // 4096
#define OW      (NH*DVD)          // 2048
#define SCALE_F 0.07216878364870323f

// ---------------- scratch ----------------
__device__ float g_q   [MROWS*QW];
__device__ float g_kvb [MROWS*KVBW];
__device__ float g_kpe [MROWS*DRD];
__device__ float g_kperaw[MROWS*DRD];
__device__ unsigned int g_eta_enc[256];
__device__ float g_eta[256];
// fragment-packed operands (tf32-rounded)
__device__ float g_xpk   [MROWS*DMODEL];
__device__ float g_qlatpk[MROWS*QLAT];
__device__ float g_kvapk [MROWS*KVLAT];
__device__ float g_attnpk[MROWS*OW];
__device__ float g_wqapk [QLAT*DMODEL];
__device__ float g_wqbpk [QW*QLAT];
__device__ float g_wkapk [KVAP*DMODEL];
__device__ float g_wkbpk [KVBW*KVLAT];
__device__ float g_wopk  [DMODEL*OW];

// ---------------- helpers ----------------
__device__ __forceinline__ float silu_f(float x) { return x / (1.0f + expf(-x)); }

__device__ __forceinline__ unsigned encf(float f) {
    unsigned u = __float_as_uint(f);
    return (u & 0x80000000u) ? ~u : (u | 0x80000000u);
}
__device__ __forceinline__ float decf(unsigned u) {
    return (u & 0x80000000u) ? __uint_as_float(u ^ 0x80000000u) : __uint_as_float(~u);
}
__device__ __forceinline__ uint32_t smem_u32(const void* p) {
    uint32_t a;
    asm("{ .reg .u64 t; cvta.to.shared.u64 t, %1; cvt.u32.u64 %0, t; }" : "=r"(a) : "l"(p));
    return a;
}
__device__ __forceinline__ void cpasync16(uint32_t dst, const void* src) {
    asm volatile("cp.async.cg.shared.global [%0], [%1], 16;" :: "r"(dst), "l"(src));
}
__device__ __forceinline__ void cp_commit() { asm volatile("cp.async.commit_group;" ::: "memory"); }
__device__ __forceinline__ void cp_wait1()  { asm volatile("cp.async.wait_group 1;"  ::: "memory"); }

__device__ __forceinline__ uint32_t f2tf(float f) {
    uint32_t r;
    asm("cvt.rna.tf32.f32 %0, %1;" : "=r"(r) : "f"(f));
    return r;
}
__device__ __forceinline__ float f2tff(float f) { return __uint_as_float(f2tf(f)); }

__device__ __forceinline__ void mma8(float* d, const uint32_t* a, const uint32_t* b) {
    asm volatile("mma.sync.aligned.m16n8k8.row.col.f32.tf32.tf32.f32 "
        "{%0,%1,%2,%3},{%4,%5,%6,%7},{%8,%9},{%0,%1,%2,%3};"
        : "+f"(d[0]), "+f"(d[1]), "+f"(d[2]), "+f"(d[3])
        : "r"(a[0]), "r"(a[1]), "r"(a[2]), "r"(a[3]), "r"(b[0]), "r"(b[1]));
}

// packed-A element index: m,k -> offset (Kt = K/8 tiles)
__device__ __forceinline__ size_t a_pk_idx(int m, int k, int Kt) {
    int tm = m >> 4, rr = m & 15, lr = rr & 7, hi = rr >> 3;
    int tk = k >> 3, k7 = k & 7, qk = (k7 >> 2) << 1, lc = k7 & 3;
    return ((size_t)tm * Kt + tk) * 128 + (lr * 4 + lc) * 4 + qk + hi;
}

// ---------------- pack kernels (round to tf32) ----------------
__global__ void pack_a_k(const float* __restrict__ src, float* __restrict__ dst, int Kt, int ld, int n) {
    int o = blockIdx.x * blockDim.x + threadIdx.x;
    if (o >= n) return;
    int tile = o >> 7, l4q = o & 127, l = l4q >> 2, q = l4q & 3;
    int tm = tile / Kt, tk = tile % Kt;
    int r = tm * 16 + (q & 1) * 8 + (l >> 2);
    int k = tk * 8 + (q >> 1) * 4 + (l & 3);
    dst[o] = f2tff(src[(size_t)r * ld + k]);
}

__global__ void pack_b_k(const float* __restrict__ src, float* __restrict__ dst, int Kt, int ld, int N, int n) {
    int o = blockIdx.x * blockDim.x + threadIdx.x;
    if (o >= n) return;
    int tile = o >> 6, lq = o & 63, l = lq >> 1, q = lq & 1;
    int tn = tile / Kt, tk = tile % Kt;
    int nr = tn * 8 + (l >> 2);
    int k = tk * 8 + q * 4 + (l & 3);
    dst[o] = (nr < N) ? f2tff(src[(size_t)nr * ld + k]) : 0.0f;
}

// ---------------- packed tf32 GEMM: C[M,N] = A[M,K] @ B[N,K]^T ----------------
// BM=256, BN=128, BK=32, 512 threads (16 warps, 64x32 each), 3 stages, 1 CTA/SM.
// EPI: 0=plain  1=packed-A out(Kt=64)  2=Q silu/rope + eta  3=kva packed + kperaw  4=kvb silu + eta
#define STAGE_B 49152
#define GEMM_SMEM (3*STAGE_B)     // 144 KB

template<int EPI>
__global__ void __launch_bounds__(512, 1)
gemm_pk(const float* __restrict__ A, const float* __restrict__ B, float* __restrict__ C,
        float* __restrict__ C2, int N, int K, const float* __restrict__ fc)
{
    extern __shared__ float sm[];
    uint32_t sb = smem_u32(sm);
    int Kt = K >> 3;

    int tid  = threadIdx.x;
    int bm   = blockIdx.y * 256;
    int bn   = blockIdx.x * 128;
    int wid  = tid >> 5, lane = tid & 31;
    int wm   = (wid >> 2) * 64;
    int wn   = (wid & 3) * 32;
    int lr   = lane >> 2, lc = lane & 3;

    float acc[4][4][4];
#pragma unroll
    for (int t = 0; t < 4; t++)
#pragma unroll
        for (int j = 0; j < 4; j++)
#pragma unroll
            for (int v = 0; v < 4; v++) acc[t][j][v] = 0.f;

    auto loadStage = [&](int s, int ko) {
        uint32_t abase = sb + s * STAGE_B;
        uint32_t bbase = abase + 32768;
        int kt0 = ko >> 3;
#pragma unroll
        for (int j = 0; j < 4; j++) {
            int idx = j * 512 + tid;
            int tm = idx >> 7, u = idx & 127;
            const float* src = A + ((size_t)(bm / 16 + tm) * Kt + kt0) * 128 + u * 4;
            cpasync16(abase + tm * 2048 + u * 16, src);
        }
#pragma unroll
        for (int j = 0; j < 2; j++) {
            int idx = j * 512 + tid;
            int tn = idx >> 6, u = idx & 63;
            const float* src = B + ((size_t)(bn / 8 + tn) * Kt + kt0) * 64 + u * 4;
            cpasync16(bbase + tn * 1024 + u * 16, src);
        }
    };

    int nk = K / 32;
    loadStage(0, 0);  cp_commit();
    loadStage(1, 32); cp_commit();

    for (int i = 0; i < nk; i++) {
        int s = i % 3;
        cp_wait1();
        __syncthreads();
        if (i + 2 < nk) loadStage((i + 2) % 3, (i + 2) * 32);
        cp_commit();

        const float* as = sm + s * (STAGE_B/4);
        const float* bs = as + 8192;
#pragma unroll
        for (int ks = 0; ks < 4; ks++) {
            uint32_t af[4][4], bf[4][2];
#pragma unroll
            for (int t = 0; t < 4; t++) {
                float4 v = *(const float4*)(as + ((wm >> 4) + t) * 512 + ks * 128 + lane * 4);
                af[t][0] = __float_as_uint(v.x); af[t][1] = __float_as_uint(v.y);
                af[t][2] = __float_as_uint(v.z); af[t][3] = __float_as_uint(v.w);
            }
#pragma unroll
            for (int j = 0; j < 4; j++) {
                float2 v = *(const float2*)(bs + ((wn >> 3) + j) * 256 + ks * 64 + lane * 2);
                bf[j][0] = __float_as_uint(v.x); bf[j][1] = __float_as_uint(v.y);
            }
#pragma unroll
            for (int t = 0; t < 4; t++)
#pragma unroll
                for (int j = 0; j < 4; j++)
                    mma8(acc[t][j], af[t], bf[j]);
        }
    }

    // epilogue (+ optional fused eta max)
    float mnope = -FLT_MAX, mpe = -FLT_MAX;
#pragma unroll
    for (int t = 0; t < 4; t++) {
        int row0 = bm + wm + t * 16 + lr;
#pragma unroll
        for (int j = 0; j < 4; j++) {
            int col = bn + wn + j * 8 + lc * 2;
            float v0 = acc[t][j][0], v1 = acc[t][j][1], v2 = acc[t][j][2], v3 = acc[t][j][3];
            if (EPI == 0) {
                *(float2*)&C[(size_t)row0 * N + col]       = make_float2(v0, v1);
                *(float2*)&C[(size_t)(row0 + 8) * N + col] = make_float2(v2, v3);
            } else if (EPI == 1) {
                int tm = (bm + wm + t * 16) >> 4;
                int tk = col >> 3;
                int lp = lr * 4 + ((col & 7) & 3);
                int qk = (col & 4) >> 1;
                size_t base = ((size_t)tm * 64 + tk) * 128;
                *(float2*)&C[base + lp * 4 + qk]       = make_float2(f2tff(v0), f2tff(v2));
                *(float2*)&C[base + (lp + 1) * 4 + qk] = make_float2(f2tff(v1), f2tff(v3));
            } else if (EPI == 2) {
                int d = col % 192;
                if (d < DN) {
                    v0 = silu_f(v0); v1 = silu_f(v1); v2 = silu_f(v2); v3 = silu_f(v3);
                    mnope = fmaxf(mnope, fmaxf(fmaxf(v0, v1), fmaxf(v2, v3)));
                } else {
                    int p = (d - DN) >> 1;
                    int s0 = row0 & (SEQ - 1), s1 = (row0 + 8) & (SEQ - 1);
                    float c0 = fc[s0*64 + p*2], n0 = fc[s0*64 + p*2 + 1];
                    float c1 = fc[s1*64 + p*2], n1 = fc[s1*64 + p*2 + 1];
                    float r0 = v0*c0 - v1*n0, i0 = v0*n0 + v1*c0;
                    float r1 = v2*c1 - v3*n1, i1 = v2*n1 + v3*c1;
                    v0 = silu_f(r0); v1 = silu_f(i0); v2 = silu_f(r1); v3 = silu_f(i1);
                    mpe = fmaxf(mpe, fmaxf(fmaxf(v0, v1), fmaxf(v2, v3)));
                }
                *(float2*)&C[(size_t)row0 * N + col]       = make_float2(v0, v1);
                *(float2*)&C[(size_t)(row0 + 8) * N + col] = make_float2(v2, v3);
            } else if (EPI == 3) {
                if (col < KVLAT) {
                    int tm = (bm + wm + t * 16) >> 4;
                    int tk = col >> 3;
                    int lp = lr * 4 + ((col & 7) & 3);
                    int qk = (col & 4) >> 1;
                    size_t base = ((size_t)tm * 64 + tk) * 128;
                    *(float2*)&C[base + lp * 4 + qk]       = make_float2(f2tff(v0), f2tff(v2));
                    *(float2*)&C[base + (lp + 1) * 4 + qk] = make_float2(f2tff(v1), f2tff(v3));
                } else if (col < KVAW) {
                    *(float2*)&C2[(size_t)row0 * DRD + col - KVLAT]       = make_float2(v0, v1);
                    *(float2*)&C2[(size_t)(row0 + 8) * DRD + col - KVLAT] = make_float2(v2, v3);
                }
            } else if (EPI == 4) {
                int d = col % 256;
                if (d < DN) {
                    v0 = silu_f(v0); v1 = silu_f(v1); v2 = silu_f(v2); v3 = silu_f(v3);
                    mnope = fmaxf(mnope, fmaxf(fmaxf(v0, v1), fmaxf(v2, v3)));
                }
                *(float2*)&C[(size_t)row0 * N + col]       = make_float2(v0, v1);
                *(float2*)&C[(size_t)(row0 + 8) * N + col] = make_float2(v2, v3);
            }
        }
    }

    if (EPI == 2 || EPI == 4) {
        // CTA covers rows [bm, bm+256) = exactly eta group bm/256
        __syncthreads();
        sm[tid] = mnope;
        if (EPI == 2) sm[512 + tid] = mpe;
        __syncthreads();
        for (int st = 256; st > 0; st >>= 1) {
            if (tid < st) {
                sm[tid] = fmaxf(sm[tid], sm[tid + st]);
                if (EPI == 2) sm[512 + tid] = fmaxf(sm[512 + tid], sm[512 + tid + st]);
            }
            __syncthreads();
        }
        if (tid == 0) {
            int grp = bm >> 8;
            atomicMax(&g_eta_enc[(EPI == 2 ? 0 : 1) * 64 + grp], encf(sm[0]));
            if (EPI == 2) atomicMax(&g_eta_enc[2 * 64 + grp], encf(sm[512]));
        }
    }
}

// ---------------- rope+silu for k_pe + fused eta(t3) ----------------
__global__ void rope_silu_kpe_k(const float* __restrict__ fc) {
    __shared__ float red[256];
    int i = blockIdx.x * blockDim.x + threadIdx.x;
    int m = i >> 5;
    int p = i & 31;
    int s = m & (SEQ - 1);
    float c = fc[s*64 + p*2 + 0];
    float sn = fc[s*64 + p*2 + 1];
    float xr = g_kperaw[(size_t)m*DRD + 2*p];
    float xi = g_kperaw[(size_t)m*DRD + 2*p + 1];
    float y0 = silu_f(xr*c - xi*sn);
    float y1 = silu_f(xr*sn + xi*c);
    g_kpe[(size_t)m*DRD + 2*p]     = y0;
    g_kpe[(size_t)m*DRD + 2*p + 1] = y1;
    red[threadIdx.x] = fmaxf(y0, y1);
    __syncthreads();
    for (int st = 128; st > 0; st >>= 1) {
        if (threadIdx.x < st) red[threadIdx.x] = fmaxf(red[threadIdx.x], red[threadIdx.x + st]);
        __syncthreads();
    }
    if (threadIdx.x == 0) {
        int grp = blockIdx.x >> 5;      // 8 rows per block, 256 rows per group
        atomicMax(&g_eta_enc[3*64 + grp], encf(red[0]));
    }
}

// ---------------- eta ----------------
__global__ void eta_init_k() {
    if (threadIdx.x < 256) g_eta_enc[threadIdx.x] = 0u;
}

__global__ void eta_fin_k() {
    int i = threadIdx.x;
    if (i < 256) {
        float m = decf(g_eta_enc[i]);
        if (m == 0.0f) m = 1e-6f;
        g_eta[i] = fminf(10.0f / m, 1.0f);
    }
}

// ---------------- block attention (output packed for GEMM5 A) ----------------
__global__ void __launch_bounds__(256) attn_kernel() {
    __shared__ float sA[64*65];
    __shared__ float sB[64*65];
    int bnb = blockIdx.x;
    int h   = blockIdx.y;
    int b = bnb >> 6, n = bnb & 63;
    int m0 = b*SEQ + n*64;
    int tid = threadIdx.x;
    int ty = tid >> 4, tx = tid & 15;

    float eqn = g_eta[  0 + b*16 + h];
    float ekn = g_eta[ 64 + b*16 + h];
    float eqp = g_eta[128 + b*16 + h];
    float ekp = g_eta[192 + b*16 + h];

    float c_pe[4][4], c_np[4][4];
#pragma unroll
    for (int i = 0; i < 4; i++)
#pragma unroll
        for (int j = 0; j < 4; j++) { c_pe[i][j] = 0.f; c_np[i][j] = 0.f; }

    for (int idx = tid; idx < 4096; idx += 256) {
        int q = idx >> 6, d = idx & 63;
        sA[d*65 + q] = g_q[(size_t)(m0+q)*QW + h*192 + DN + d];
        sB[d*65 + q] = g_kpe[(size_t)(m0+q)*DRD + d];
    }
    __syncthreads();
#pragma unroll 4
    for (int k = 0; k < 64; k++) {
        float a[4], bb[4];
#pragma unroll
        for (int i = 0; i < 4; i++) a[i]  = sA[k*65 + ty*4 + i];
#pragma unroll
        for (int j = 0; j < 4; j++) bb[j] = sB[k*65 + tx*4 + j];
#pragma unroll
        for (int i = 0; i < 4; i++)
#pragma unroll
            for (int j = 0; j < 4; j++)
                c_pe[i][j] = fmaf(a[i], bb[j], c_pe[i][j]);
    }
    __syncthreads();

    for (int ch = 0; ch < 2; ch++) {
        for (int idx = tid; idx < 4096; idx += 256) {
            int q = idx >> 6, d = idx & 63;
            sA[d*65 + q] = g_q  [(size_t)(m0+q)*QW   + h*192 + ch*64 + d];
            sB[d*65 + q] = g_kvb[(size_t)(m0+q)*KVBW + h*256 + ch*64 + d];
        }
        __syncthreads();
#pragma unroll 4
        for (int k = 0; k < 64; k++) {
            float a[4], bb[4];
#pragma unroll
            for (int i = 0; i < 4; i++) a[i]  = sA[k*65 + ty*4 + i];
#pragma unroll
            for (int j = 0; j < 4; j++) bb[j] = sB[k*65 + tx*4 + j];
#pragma unroll
            for (int i = 0; i < 4; i++)
#pragma unroll
                for (int j = 0; j < 4; j++)
                    c_np[i][j] = fmaf(a[i], bb[j], c_np[i][j]);
        }
        __syncthreads();
    }

    float fn = eqn * ekn * SCALE_F;
    float fp = eqp * ekp * SCALE_F;
#pragma unroll
    for (int i = 0; i < 4; i++)
#pragma unroll
        for (int j = 0; j < 4; j++) {
            int q = ty*4 + i, kk = tx*4 + j;
            float v = c_np[i][j]*fn + c_pe[i][j]*fp;
            if (kk > q) v = -3.402823466e38f;
            sA[q*65 + kk] = v;
        }
    __syncthreads();

    {
        int w = tid >> 5, lane = tid & 31;
        for (int r = w; r < 64; r += 8) {
            float x0 = sA[r*65 + lane];
            float x1 = sA[r*65 + lane + 32];
            float mx = fmaxf(x0, x1);
#pragma unroll
            for (int o = 16; o > 0; o >>= 1)
                mx = fmaxf(mx, __shfl_xor_sync(0xffffffffu, mx, o));
            float e0 = expf(x0 - mx);
            float e1 = expf(x1 - mx);
            float sm = e0 + e1;
#pragma unroll
            for (int o = 16; o > 0; o >>= 1)
                sm += __shfl_xor_sync(0xffffffffu, sm, o);
            float inv = 1.0f / sm;
            sA[r*65 + lane]      = e0 * inv;
            sA[r*65 + lane + 32] = e1 * inv;
        }
    }
    __syncthreads();

    for (int ch = 0; ch < 2; ch++) {
        for (int idx = tid; idx < 4096; idx += 256) {
            int kk = idx >> 6, d = idx & 63;
            sB[kk*65 + d] = g_kvb[(size_t)(m0+kk)*KVBW + h*256 + DN + ch*64 + d];
        }
        __syncthreads();
        float o[4][4];
#pragma unroll
        for (int i = 0; i < 4; i++)
#pragma unroll
            for (int j = 0; j < 4; j++) o[i][j] = 0.f;
#pragma unroll 4
        for (int k = 0; k < 64; k++) {
            float a[4], bb[4];
#pragma unroll
            for (int i = 0; i < 4; i++) a[i]  = sA[(ty*4 + i)*65 + k];
#pragma unroll
            for (int j = 0; j < 4; j++) bb[j] = sB[k*65 + tx*4 + j];
#pragma unroll
            for (int i = 0; i < 4; i++)
#pragma unroll
                for (int j = 0; j < 4; j++)
                    o[i][j] = fmaf(a[i], bb[j], o[i][j]);
        }
#pragma unroll
        for (int i = 0; i < 4; i++) {
            int m = m0 + ty*4 + i;
            int kk0 = h*DVD + ch*64 + tx*4;
#pragma unroll
            for (int j = 0; j < 4; j++)
                g_attnpk[a_pk_idx(m, kk0 + j, 256)] = f2tff(o[i][j]);
        }
        __syncthreads();
    }
}

// ---------------- launch ----------------
extern "C" void kernel_launch(void* const* d_in, const int* in_sizes, int n_in,
                              void* d_out, int out_size)
{
    const float* x     = (const float*)d_in[0];
    const float* fc    = (const float*)d_in[1];
    const float* wq_a  = (const float*)d_in[2];
    const float* wq_b  = (const float*)d_in[3];
    const float* wkv_a = (const float*)d_in[4];
    const float* wkv_b = (const float*)d_in[5];
    const float* wo    = (const float*)d_in[6];
    float* out = (float*)d_out;

    float *q, *kvb, *kperaw;
    float *xpk, *qlatpk, *kvapk, *attnpk;
    float *wqapk, *wqbpk, *wkapk, *wkbpk, *wopk;
    cudaGetSymbolAddress((void**)&q,      g_q);
    cudaGetSymbolAddress((void**)&kvb,    g_kvb);
    cudaGetSymbolAddress((void**)&kperaw, g_kperaw);
    cudaGetSymbolAddress((void**)&xpk,    g_xpk);
    cudaGetSymbolAddress((void**)&qlatpk, g_qlatpk);
    cudaGetSymbolAddress((void**)&kvapk,  g_kvapk);
    cudaGetSymbolAddress((void**)&attnpk, g_attnpk);
    cudaGetSymbolAddress((void**)&wqapk,  g_wqapk);
    cudaGetSymbolAddress((void**)&wqbpk,  g_wqbpk);
    cudaGetSymbolAddress((void**)&wkapk,  g_wkapk);
    cudaGetSymbolAddress((void**)&wkbpk,  g_wkbpk);
    cudaGetSymbolAddress((void**)&wopk,   g_wopk);

    cudaFuncSetAttribute(gemm_pk<0>, cudaFuncAttributeMaxDynamicSharedMemorySize, GEMM_SMEM);
    cudaFuncSetAttribute(gemm_pk<1>, cudaFuncAttributeMaxDynamicSharedMemorySize, GEMM_SMEM);
    cudaFuncSetAttribute(gemm_pk<2>, cudaFuncAttributeMaxDynamicSharedMemorySize, GEMM_SMEM);
    cudaFuncSetAttribute(gemm_pk<3>, cudaFuncAttributeMaxDynamicSharedMemorySize, GEMM_SMEM);
    cudaFuncSetAttribute(gemm_pk<4>, cudaFuncAttributeMaxDynamicSharedMemorySize, GEMM_SMEM);

    // packs
    pack_a_k<<<(MROWS*DMODEL)/256, 256>>>(x, xpk, DMODEL/8, DMODEL, MROWS*DMODEL);
    pack_b_k<<<(QLAT*DMODEL)/256, 256>>>(wq_a, wqapk, DMODEL/8, DMODEL, QLAT, QLAT*DMODEL);
    pack_b_k<<<(QW*QLAT)/256, 256>>>(wq_b, wqbpk, QLAT/8, QLAT, QW, QW*QLAT);
    pack_b_k<<<(KVAP*DMODEL)/256, 256>>>(wkv_a, wkapk, DMODEL/8, DMODEL, KVAW, KVAP*DMODEL);
    pack_b_k<<<(KVBW*KVLAT)/256, 256>>>(wkv_b, wkbpk, KVLAT/8, KVLAT, KVBW, KVBW*KVLAT);
    eta_init_k<<<1, 256>>>();

    // q_lat = x @ wq_a^T  [16384,512] K=2048 -> packed
    gemm_pk<1><<<dim3(4, 64), 512, GEMM_SMEM>>>(xpk, wqapk, qlatpk, nullptr, QLAT, DMODEL, nullptr);
    // q = q_lat @ wq_b^T  [16384,3072] K=512 -> row-major + silu/rope + eta(0,2)
    gemm_pk<2><<<dim3(24, 64), 512, GEMM_SMEM>>>(qlatpk, wqbpk, q, nullptr, QW, QLAT, fc);
    // kv_a = x @ wkv_a^T  [16384,640] K=2048 -> packed kv_c + raw k_pe
    gemm_pk<3><<<dim3(5, 64), 512, GEMM_SMEM>>>(xpk, wkapk, kvapk, kperaw, KVAP, DMODEL, nullptr);
    // kvb = kv_c @ wkv_b^T  [16384,4096] K=512 -> row-major + silu + eta(1)
    gemm_pk<4><<<dim3(32, 64), 512, GEMM_SMEM>>>(kvapk, wkbpk, kvb, nullptr, KVBW, KVLAT, nullptr);

    rope_silu_kpe_k<<<(MROWS*32)/256, 256>>>(fc);
    eta_fin_k<<<1, 256>>>();

    attn_kernel<<<dim3(BQ*64, NH), 256>>>();

    pack_b_k<<<(DMODEL*OW)/256, 256>>>(wo, wopk, OW/8, OW, DMODEL, DMODEL*OW);
    // out = attn_out @ wo^T  [16384,2048] K=2048
    gemm_pk<0><<<dim3(16, 64), 512, GEMM_SMEM>>>(attnpk, wopk, out, nullptr, DMODEL, OW, nullptr);
}